// round 1
// baseline (speedup 1.0000x reference)
#include <cuda_runtime.h>
#include <math.h>

#define Bx    8
#define Nn    784
#define Cc    768
#define Hh    12
#define DhD   64
#define TOPKK 100
#define MROWS (Bx*Nn)     // 6272
#define QKVC  (3*Cc)      // 2304
#define BHB   (Bx*Hh)     // 96

// Scratch (allocation-free rule: __device__ globals)
__device__ float g_Y[(size_t)MROWS * QKVC];       // qkv projection output
__device__ float g_S[(size_t)BHB * Nn * Nn];      // raw scores (B,H,N,N)
__device__ float g_CTX[(size_t)MROWS * Cc];       // context in (B,N,C) layout

// ---------------- generic NT GEMM: C[M,N] = A[M,K] * B[N,K]^T (+bias) ----------------
// Requires M%64==0, N%64==0, K%16==0. 256 threads, 64x64 tile, 4x4 per thread.
__global__ __launch_bounds__(256) void gemm_nt_kernel(
    const float* __restrict__ A, int lda,
    const float* __restrict__ B, int ldb,
    float* __restrict__ C, int ldc,
    int K, const float* __restrict__ bias)
{
    __shared__ float As[16][68];
    __shared__ float Bs[16][68];
    const int m0 = blockIdx.y * 64, n0 = blockIdx.x * 64;
    const int tid = threadIdx.x;
    const int row = tid >> 2, c4 = (tid & 3) * 4;
    const int ty = tid >> 4, tx = tid & 15;
    float acc[4][4] = {};
    const float* Ap = A + (size_t)(m0 + row) * lda + c4;
    const float* Bp = B + (size_t)(n0 + row) * ldb + c4;
    for (int k0 = 0; k0 < K; k0 += 16) {
        float4 a = *(const float4*)(Ap + k0);
        float4 b = *(const float4*)(Bp + k0);
        As[c4+0][row]=a.x; As[c4+1][row]=a.y; As[c4+2][row]=a.z; As[c4+3][row]=a.w;
        Bs[c4+0][row]=b.x; Bs[c4+1][row]=b.y; Bs[c4+2][row]=b.z; Bs[c4+3][row]=b.w;
        __syncthreads();
        #pragma unroll
        for (int k = 0; k < 16; ++k) {
            float4 av = *(const float4*)&As[k][ty*4];
            float4 bv = *(const float4*)&Bs[k][tx*4];
            float am[4] = {av.x, av.y, av.z, av.w};
            float bm[4] = {bv.x, bv.y, bv.z, bv.w};
            #pragma unroll
            for (int i = 0; i < 4; ++i)
                #pragma unroll
                for (int j = 0; j < 4; ++j)
                    acc[i][j] += am[i] * bm[j];
        }
        __syncthreads();
    }
    #pragma unroll
    for (int i = 0; i < 4; ++i) {
        int mm = m0 + ty*4 + i;
        #pragma unroll
        for (int j = 0; j < 4; ++j) {
            int nn = n0 + tx*4 + j;
            float v = acc[i][j];
            if (bias) v += bias[nn];
            C[(size_t)mm * ldc + nn] = v;
        }
    }
}

// ---------------- scores: S[b,h,n,m] = 0.125 * q[b,h,n,:] . k[b,h,m,:] ----------------
__global__ __launch_bounds__(256) void scores_kernel(
    const float* __restrict__ Y, float* __restrict__ S)
{
    __shared__ float Qs[64][68];
    __shared__ float Ks[64][68];
    const int z = blockIdx.z;             // b*H + h
    const int b = z / Hh, h = z % Hh;
    const int m0 = blockIdx.y * 64;       // query tile
    const int n0 = blockIdx.x * 64;       // key tile
    const int tid = threadIdx.x;
    const int row = tid >> 2, cbase = (tid & 3) * 16;

    const int qr = m0 + row;
    const int kr = n0 + row;
    const bool qok = qr < Nn, kok = kr < Nn;
    const float* qp = Y + (size_t)(b*Nn + qr) * QKVC + h*DhD;
    const float* kp = Y + (size_t)(b*Nn + kr) * QKVC + Cc + h*DhD;
    #pragma unroll
    for (int j = 0; j < 4; ++j) {
        int col = cbase + j*4;
        float4 qa = qok ? *(const float4*)(qp + col) : make_float4(0,0,0,0);
        float4 ka = kok ? *(const float4*)(kp + col) : make_float4(0,0,0,0);
        Qs[col+0][row]=qa.x; Qs[col+1][row]=qa.y; Qs[col+2][row]=qa.z; Qs[col+3][row]=qa.w;
        Ks[col+0][row]=ka.x; Ks[col+1][row]=ka.y; Ks[col+2][row]=ka.z; Ks[col+3][row]=ka.w;
    }
    __syncthreads();

    const int ty = tid >> 4, tx = tid & 15;
    float acc[4][4] = {};
    #pragma unroll
    for (int k = 0; k < 64; ++k) {
        float4 av = *(const float4*)&Qs[k][ty*4];
        float4 bv = *(const float4*)&Ks[k][tx*4];
        float am[4] = {av.x, av.y, av.z, av.w};
        float bm[4] = {bv.x, bv.y, bv.z, bv.w};
        #pragma unroll
        for (int i = 0; i < 4; ++i)
            #pragma unroll
            for (int j = 0; j < 4; ++j)
                acc[i][j] += am[i] * bm[j];
    }
    #pragma unroll
    for (int i = 0; i < 4; ++i) {
        int nq = m0 + ty*4 + i;
        if (nq >= Nn) continue;
        #pragma unroll
        for (int j = 0; j < 4; ++j) {
            int mk = n0 + tx*4 + j;
            if (mk >= Nn) continue;
            S[((size_t)z * Nn + nq) * Nn + mk] = acc[i][j] * 0.125f;
        }
    }
}

// ---------------- zero score_delta region ----------------
__global__ void zero_kernel(float4* __restrict__ p, int n4)
{
    int i = blockIdx.x * blockDim.x + threadIdx.x;
    if (i < n4) p[i] = make_float4(0.f, 0.f, 0.f, 0.f);
}

// ---------------- per-row UCB top-k + pruned-softmax context + score_delta ----------------
__global__ __launch_bounds__(256) void topk_ctx_kernel(
    const float* __restrict__ Y,
    const float* __restrict__ S,
    const float* __restrict__ ucb,
    const int* __restrict__ counter_p,
    float* __restrict__ ctx,
    float* __restrict__ sd)
{
    __shared__ float    s_val[Nn];
    __shared__ unsigned s_key[Nn];
    __shared__ int      sel_idx[TOPKK];
    __shared__ float    sel_w[TOPKK];
    __shared__ int      sred[8];
    __shared__ float    s_inv;
    __shared__ float    part[4][DhD];

    const int bid = blockIdx.x;
    const int n = bid % Nn;
    const int z = bid / Nn;                // b*H + h
    const int b = z / Hh, h = z % Hh;
    const int tid = threadIdx.x;

    const float logc = logf((float)(*counter_p));

    // load row: raw score + orderable key of (score + ucb bonus)
    const float* srow = S + ((size_t)z * Nn + n) * Nn;
    const float* urow = ucb + ((size_t)h * Nn + n) * Nn;
    for (int i = tid; i < Nn; i += 256) {
        float s = srow[i];
        float u = s + sqrtf(logc / (urow[i] + 1e-6f));
        s_val[i] = s;
        unsigned ub = __float_as_uint(u);
        s_key[i] = (ub & 0x80000000u) ? ~ub : (ub | 0x80000000u);
    }
    __syncthreads();

    // bitwise radix-select: key of the 100th-largest element
    unsigned prefix = 0; int want = TOPKK;
    for (int bit = 31; bit >= 0; --bit) {
        unsigned mask = ~((1u << bit) - 1u);
        unsigned test = prefix | (1u << bit);
        int c = 0;
        for (int i = tid; i < Nn; i += 256)
            c += ((s_key[i] & mask) == test);
        c = __reduce_add_sync(0xffffffffu, c);
        if ((tid & 31) == 0) sred[tid >> 5] = c;
        __syncthreads();
        int tot = sred[0]+sred[1]+sred[2]+sred[3]+sred[4]+sred[5]+sred[6]+sred[7];
        if (tot >= want) prefix = test; else want -= tot;
        __syncthreads();
    }
    const unsigned tkey = prefix;   // exact key of k-th largest; `want` ties still needed

    // warp 0: deterministic index-ordered compaction (+ exact tie handling, lowest index first)
    if (tid < 32) {
        const int lane = tid;
        int cnt = 0, eq_seen = 0;
        const int need_eq = want;
        for (int base = 0; base < Nn; base += 32) {
            int i = base + lane;
            unsigned key = (i < Nn) ? s_key[i] : 0u;
            bool gt = (i < Nn) && (key > tkey);
            bool eq = (i < Nn) && (key == tkey);
            unsigned eqm = __ballot_sync(0xffffffffu, eq);
            int eq_rank = __popc(eqm & ((1u << lane) - 1u));
            bool sel = gt || (eq && (eq_seen + eq_rank) < need_eq);
            unsigned selm = __ballot_sync(0xffffffffu, sel);
            int pos = cnt + __popc(selm & ((1u << lane) - 1u));
            if (sel && pos < TOPKK) sel_idx[pos] = i;
            cnt += __popc(selm);
            eq_seen += __popc(eqm);
        }
        // deterministic sum of selected raw scores
        float ssum = 0.f;
        for (int j = lane; j < TOPKK; j += 32) ssum += s_val[sel_idx[j]];
        #pragma unroll
        for (int o = 16; o; o >>= 1) ssum += __shfl_xor_sync(0xffffffffu, ssum, o);
        if (lane == 0) s_inv = 1.0f / (ssum + 1e-8f);
    }
    __syncthreads();

    // normalized weights + score_delta
    if (tid < TOPKK) {
        sel_w[tid] = s_val[sel_idx[tid]] * s_inv;
        atomicAdd(&sd[((size_t)h * Nn + n) * Nn + sel_idx[tid]], 1.0f);
    }
    __syncthreads();

    // context gather: ctx[b,n,h*64+d] = sum_j w_j * v[b,j,h,d]
    const int d = tid & 63, g = tid >> 6;  // 4 groups of 25 selected each
    float acc = 0.f;
    const float* vbase = Y + (size_t)(b * Nn) * QKVC + 2*Cc + h*DhD + d;
    #pragma unroll 5
    for (int j = g*25; j < g*25 + 25; ++j)
        acc += sel_w[j] * vbase[(size_t)sel_idx[j] * QKVC];
    part[g][d] = acc;
    __syncthreads();
    if (tid < DhD) {
        float v = (part[0][tid] + part[1][tid]) + (part[2][tid] + part[3][tid]);
        ctx[((size_t)(b*Nn + n)) * Cc + h*DhD + tid] = v;
    }
}

extern "C" void kernel_launch(void* const* d_in, const int* in_sizes, int n_in,
                              void* d_out, int out_size)
{
    const float* x      = (const float*)d_in[0];
    const float* ucb    = (const float*)d_in[1];
    const float* qkv_w  = (const float*)d_in[2];
    const float* proj_w = (const float*)d_in[3];
    const float* proj_b = (const float*)d_in[4];
    const int*   counter = (const int*)d_in[5];
    float* out = (float*)d_out;
    float* sd  = out + (size_t)MROWS * Cc;   // score_delta region follows `out`

    float *Y, *S, *CTX;
    cudaGetSymbolAddress((void**)&Y,   g_Y);
    cudaGetSymbolAddress((void**)&S,   g_S);
    cudaGetSymbolAddress((void**)&CTX, g_CTX);

    // 1) qkv projection: Y[6272,2304] = x[6272,768] @ qkv_w[2304,768]^T
    gemm_nt_kernel<<<dim3(QKVC/64, MROWS/64), 256>>>(x, Cc, qkv_w, Cc, Y, QKVC, Cc, nullptr);

    // 2) scores: 96 batched 784x784x64 GEMMs
    scores_kernel<<<dim3(13, 13, BHB), 256>>>(Y, S);

    // 3) zero score_delta
    {
        int n4 = (Hh * Nn * Nn) / 4;
        zero_kernel<<<(n4 + 255) / 256, 256>>>((float4*)sd, n4);
    }

    // 4) per-row top-100 + pruned normalize + context + score_delta
    topk_ctx_kernel<<<BHB * Nn, 256>>>(Y, S, ucb, counter, CTX, sd);

    // 5) output projection: out = CTX @ proj_w^T + proj_b
    gemm_nt_kernel<<<dim3(Cc/64, MROWS/64), 256>>>(CTX, Cc, proj_w, Cc, out, Cc, Cc, proj_b);
}

// round 2
// speedup vs baseline: 1.3680x; 1.3680x over previous
#include <cuda_runtime.h>
#include <math.h>

#define Bx    8
#define Nn    784
#define Cc    768
#define Hh    12
#define DhD   64
#define TOPKK 100
#define MROWS (Bx*Nn)     // 6272
#define QKVC  (3*Cc)      // 2304
#define BHB   (Bx*Hh)     // 96

// Scratch (allocation-free rule: __device__ globals)
__device__ float g_Y[(size_t)MROWS * QKVC];       // qkv projection output
__device__ float g_S[(size_t)BHB * Nn * Nn];      // raw scores (B,H,N,N)
__device__ float g_CTX[(size_t)MROWS * Cc];       // context in (B,N,C) layout

// ---------------- generic NT GEMM: C[M,N] = A[M,K] * B[N,K]^T (+bias) ----------------
__global__ __launch_bounds__(256) void gemm_nt_kernel(
    const float* __restrict__ A, int lda,
    const float* __restrict__ B, int ldb,
    float* __restrict__ C, int ldc,
    int K, const float* __restrict__ bias)
{
    __shared__ float As[16][68];
    __shared__ float Bs[16][68];
    const int m0 = blockIdx.y * 64, n0 = blockIdx.x * 64;
    const int tid = threadIdx.x;
    const int row = tid >> 2, c4 = (tid & 3) * 4;
    const int ty = tid >> 4, tx = tid & 15;
    float acc[4][4] = {};
    const float* Ap = A + (size_t)(m0 + row) * lda + c4;
    const float* Bp = B + (size_t)(n0 + row) * ldb + c4;
    for (int k0 = 0; k0 < K; k0 += 16) {
        float4 a = *(const float4*)(Ap + k0);
        float4 b = *(const float4*)(Bp + k0);
        As[c4+0][row]=a.x; As[c4+1][row]=a.y; As[c4+2][row]=a.z; As[c4+3][row]=a.w;
        Bs[c4+0][row]=b.x; Bs[c4+1][row]=b.y; Bs[c4+2][row]=b.z; Bs[c4+3][row]=b.w;
        __syncthreads();
        #pragma unroll
        for (int k = 0; k < 16; ++k) {
            float4 av = *(const float4*)&As[k][ty*4];
            float4 bv = *(const float4*)&Bs[k][tx*4];
            float am[4] = {av.x, av.y, av.z, av.w};
            float bm[4] = {bv.x, bv.y, bv.z, bv.w};
            #pragma unroll
            for (int i = 0; i < 4; ++i)
                #pragma unroll
                for (int j = 0; j < 4; ++j)
                    acc[i][j] += am[i] * bm[j];
        }
        __syncthreads();
    }
    #pragma unroll
    for (int i = 0; i < 4; ++i) {
        int mm = m0 + ty*4 + i;
        #pragma unroll
        for (int j = 0; j < 4; ++j) {
            int nn = n0 + tx*4 + j;
            float v = acc[i][j];
            if (bias) v += bias[nn];
            C[(size_t)mm * ldc + nn] = v;
        }
    }
}

// ---------------- scores: S[b,h,n,m] = 0.125 * q[b,h,n,:] . k[b,h,m,:] ----------------
__global__ __launch_bounds__(256) void scores_kernel(
    const float* __restrict__ Y, float* __restrict__ S)
{
    __shared__ float Qs[64][68];
    __shared__ float Ks[64][68];
    const int z = blockIdx.z;             // b*H + h
    const int b = z / Hh, h = z % Hh;
    const int m0 = blockIdx.y * 64;       // query tile
    const int n0 = blockIdx.x * 64;       // key tile
    const int tid = threadIdx.x;
    const int row = tid >> 2, cbase = (tid & 3) * 16;

    const int qr = m0 + row;
    const int kr = n0 + row;
    const bool qok = qr < Nn, kok = kr < Nn;
    const float* qp = Y + (size_t)(b*Nn + qr) * QKVC + h*DhD;
    const float* kp = Y + (size_t)(b*Nn + kr) * QKVC + Cc + h*DhD;
    #pragma unroll
    for (int j = 0; j < 4; ++j) {
        int col = cbase + j*4;
        float4 qa = qok ? *(const float4*)(qp + col) : make_float4(0,0,0,0);
        float4 ka = kok ? *(const float4*)(kp + col) : make_float4(0,0,0,0);
        Qs[col+0][row]=qa.x; Qs[col+1][row]=qa.y; Qs[col+2][row]=qa.z; Qs[col+3][row]=qa.w;
        Ks[col+0][row]=ka.x; Ks[col+1][row]=ka.y; Ks[col+2][row]=ka.z; Ks[col+3][row]=ka.w;
    }
    __syncthreads();

    const int ty = tid >> 4, tx = tid & 15;
    float acc[4][4] = {};
    #pragma unroll
    for (int k = 0; k < 64; ++k) {
        float4 av = *(const float4*)&Qs[k][ty*4];
        float4 bv = *(const float4*)&Ks[k][tx*4];
        float am[4] = {av.x, av.y, av.z, av.w};
        float bm[4] = {bv.x, bv.y, bv.z, bv.w};
        #pragma unroll
        for (int i = 0; i < 4; ++i)
            #pragma unroll
            for (int j = 0; j < 4; ++j)
                acc[i][j] += am[i] * bm[j];
    }
    #pragma unroll
    for (int i = 0; i < 4; ++i) {
        int nq = m0 + ty*4 + i;
        if (nq >= Nn) continue;
        #pragma unroll
        for (int j = 0; j < 4; ++j) {
            int mk = n0 + tx*4 + j;
            if (mk >= Nn) continue;
            S[((size_t)z * Nn + nq) * Nn + mk] = acc[i][j] * 0.125f;
        }
    }
}

// ---------------- zero score_delta region ----------------
__global__ void zero_kernel(float4* __restrict__ p, int n4)
{
    int i = blockIdx.x * blockDim.x + threadIdx.x;
    if (i < n4) p[i] = make_float4(0.f, 0.f, 0.f, 0.f);
}

// ---------------- per-row UCB top-k + pruned-softmax context + score_delta ----------------
// Top-100 via 4-pass byte-wise histogram radix select (exact, deterministic).
__global__ __launch_bounds__(256) void topk_ctx_kernel(
    const float* __restrict__ Y,
    const float* __restrict__ S,
    const float* __restrict__ ucb,
    const int* __restrict__ counter_p,
    float* __restrict__ ctx,
    float* __restrict__ sd)
{
    __shared__ float    s_val[Nn];
    __shared__ unsigned s_key[Nn];
    __shared__ int      hist[256];
    __shared__ int      sscan[256];
    __shared__ int      sel_idx[TOPKK];
    __shared__ float    sel_w[TOPKK];
    __shared__ unsigned s_state[2];   // [0]=prefix, [1]=want
    __shared__ float    s_inv;
    __shared__ float    part[4][DhD];

    const int bid = blockIdx.x;
    const int n = bid % Nn;
    const int z = bid / Nn;                // b*H + h
    const int b = z / Hh, h = z % Hh;
    const int tid = threadIdx.x;

    const float logc = logf((float)(*counter_p));

    // init histogram for pass 3 (fused with row load)
    hist[tid] = 0;
    __syncthreads();

    // load row: raw score + orderable key of (score + ucb bonus); hist top byte
    const float* srow = S + ((size_t)z * Nn + n) * Nn;
    const float* urow = ucb + ((size_t)h * Nn + n) * Nn;
    for (int i = tid; i < Nn; i += 256) {
        float s = srow[i];
        float u = s + sqrtf(logc / (urow[i] + 1e-6f));
        s_val[i] = s;
        unsigned ub = __float_as_uint(u);
        unsigned key = (ub & 0x80000000u) ? ~ub : (ub | 0x80000000u);
        s_key[i] = key;
        atomicAdd(&hist[key >> 24], 1);
    }
    __syncthreads();

    // 4-pass radix select: find exact key of the 100th-largest element
    unsigned prefix = 0; int want = TOPKK;
    #pragma unroll
    for (int pass = 3; pass >= 0; --pass) {
        const int shift = pass * 8;
        if (pass < 3) {
            // rebuild histogram over candidates matching prefix in higher bytes
            hist[tid] = 0;
            __syncthreads();
            const int hishift = shift + 8;
            const unsigned hipfx = prefix >> hishift;
            for (int i = tid; i < Nn; i += 256) {
                unsigned key = s_key[i];
                if ((key >> hishift) == hipfx)
                    atomicAdd(&hist[(key >> shift) & 0xFFu], 1);
            }
            __syncthreads();
        }
        // suffix sums: sscan[t] = #candidates with byte >= t
        sscan[tid] = hist[tid];
        __syncthreads();
        #pragma unroll
        for (int off = 1; off < 256; off <<= 1) {
            int add = (tid + off < 256) ? sscan[tid + off] : 0;
            __syncthreads();
            sscan[tid] += add;
            __syncthreads();
        }
        // bucket b: sscan[b] >= want > sscan[b+1]
        {
            int above = (tid < 255) ? sscan[tid + 1] : 0;
            if (sscan[tid] >= want && above < want) {
                s_state[0] = prefix | ((unsigned)tid << shift);
                s_state[1] = (unsigned)(want - above);
            }
        }
        __syncthreads();
        prefix = s_state[0];
        want = (int)s_state[1];
        __syncthreads();
    }
    const unsigned tkey = prefix;   // exact key of k-th largest; `want` ties still needed

    // warp 0: deterministic index-ordered compaction (+ exact tie handling, lowest index first)
    if (tid < 32) {
        const int lane = tid;
        int cnt = 0, eq_seen = 0;
        const int need_eq = want;
        for (int base = 0; base < Nn; base += 32) {
            int i = base + lane;
            unsigned key = (i < Nn) ? s_key[i] : 0u;
            bool gt = (i < Nn) && (key > tkey);
            bool eq = (i < Nn) && (key == tkey);
            unsigned eqm = __ballot_sync(0xffffffffu, eq);
            int eq_rank = __popc(eqm & ((1u << lane) - 1u));
            bool sel = gt || (eq && (eq_seen + eq_rank) < need_eq);
            unsigned selm = __ballot_sync(0xffffffffu, sel);
            int pos = cnt + __popc(selm & ((1u << lane) - 1u));
            if (sel && pos < TOPKK) sel_idx[pos] = i;
            cnt += __popc(selm);
            eq_seen += __popc(eqm);
        }
        // deterministic sum of selected raw scores
        float ssum = 0.f;
        for (int j = lane; j < TOPKK; j += 32) ssum += s_val[sel_idx[j]];
        #pragma unroll
        for (int o = 16; o; o >>= 1) ssum += __shfl_xor_sync(0xffffffffu, ssum, o);
        if (lane == 0) s_inv = 1.0f / (ssum + 1e-8f);
    }
    __syncthreads();

    // normalized weights + score_delta
    if (tid < TOPKK) {
        sel_w[tid] = s_val[sel_idx[tid]] * s_inv;
        atomicAdd(&sd[((size_t)h * Nn + n) * Nn + sel_idx[tid]], 1.0f);
    }
    __syncthreads();

    // context gather: ctx[b,n,h*64+d] = sum_j w_j * v[b,j,h,d]
    const int d = tid & 63, g = tid >> 6;  // 4 groups of 25 selected each
    float acc = 0.f;
    const float* vbase = Y + (size_t)(b * Nn) * QKVC + 2*Cc + h*DhD + d;
    #pragma unroll 5
    for (int j = g*25; j < g*25 + 25; ++j)
        acc += sel_w[j] * vbase[(size_t)sel_idx[j] * QKVC];
    part[g][d] = acc;
    __syncthreads();
    if (tid < DhD) {
        float v = (part[0][tid] + part[1][tid]) + (part[2][tid] + part[3][tid]);
        ctx[((size_t)(b*Nn + n)) * Cc + h*DhD + tid] = v;
    }
}

extern "C" void kernel_launch(void* const* d_in, const int* in_sizes, int n_in,
                              void* d_out, int out_size)
{
    const float* x      = (const float*)d_in[0];
    const float* ucb    = (const float*)d_in[1];
    const float* qkv_w  = (const float*)d_in[2];
    const float* proj_w = (const float*)d_in[3];
    const float* proj_b = (const float*)d_in[4];
    const int*   counter = (const int*)d_in[5];
    float* out = (float*)d_out;
    float* sd  = out + (size_t)MROWS * Cc;   // score_delta region follows `out`

    float *Y, *S, *CTX;
    cudaGetSymbolAddress((void**)&Y,   g_Y);
    cudaGetSymbolAddress((void**)&S,   g_S);
    cudaGetSymbolAddress((void**)&CTX, g_CTX);

    // 1) qkv projection: Y[6272,2304] = x[6272,768] @ qkv_w[2304,768]^T
    gemm_nt_kernel<<<dim3(QKVC/64, MROWS/64), 256>>>(x, Cc, qkv_w, Cc, Y, QKVC, Cc, nullptr);

    // 2) scores: 96 batched 784x784x64 GEMMs
    scores_kernel<<<dim3(13, 13, BHB), 256>>>(Y, S);

    // 3) zero score_delta
    {
        int n4 = (Hh * Nn * Nn) / 4;
        zero_kernel<<<(n4 + 255) / 256, 256>>>((float4*)sd, n4);
    }

    // 4) per-row top-100 + pruned normalize + context + score_delta
    topk_ctx_kernel<<<BHB * Nn, 256>>>(Y, S, ucb, counter, CTX, sd);

    // 5) output projection: out = CTX @ proj_w^T + proj_b
    gemm_nt_kernel<<<dim3(Cc/64, MROWS/64), 256>>>(CTX, Cc, proj_w, Cc, out, Cc, Cc, proj_b);
}

// round 4
// speedup vs baseline: 1.3889x; 1.0153x over previous
#include <cuda_runtime.h>
#include <math.h>

#define Bx    8
#define Nn    784
#define Cc    768
#define Hh    12
#define DhD   64
#define TOPKK 100
#define MROWS (Bx*Nn)     // 6272
#define QKVC  (3*Cc)      // 2304
#define BHB   (Bx*Hh)     // 96

// Scratch (allocation-free rule: __device__ globals)
__device__ float g_Y[(size_t)MROWS * QKVC];       // qkv projection output
__device__ float g_S[(size_t)BHB * Nn * Nn];      // raw scores (B,H,N,N)
__device__ float g_CTX[(size_t)MROWS * Cc];       // context in (B,N,C) layout

// ---------------- 128x128 NT GEMM: C[M,N] = A[M,K] * B[N,K]^T (+bias) ----------------
// Requires M%128==0, N%128==0, K%16==0. 256 threads, 8x8 per thread, double-buffered.
__global__ __launch_bounds__(256) void gemm128_nt_kernel(
    const float* __restrict__ A, int lda,
    const float* __restrict__ B, int ldb,
    float* __restrict__ C, int ldc,
    int K, const float* __restrict__ bias)
{
    __shared__ float As[2][16][132];
    __shared__ float Bs[2][16][132];
    const int m0 = blockIdx.y * 128, n0 = blockIdx.x * 128;
    const int tid = threadIdx.x;
    const int ty = tid >> 4, tx = tid & 15;

    // loader mapping: tid<128 -> A row tid; tid>=128 -> B row tid-128 (16 floats per k-tile)
    const int lrow = tid & 127;
    const bool isA = tid < 128;
    const float* Lp = isA ? (A + (size_t)(m0 + lrow) * lda)
                          : (B + (size_t)(n0 + lrow) * ldb);

    float acc[8][8] = {};

    // prologue: load k-tile 0
    float4 r0 = *(const float4*)(Lp + 0);
    float4 r1 = *(const float4*)(Lp + 4);
    float4 r2 = *(const float4*)(Lp + 8);
    float4 r3 = *(const float4*)(Lp + 12);
    {
        float* pl = isA ? &As[0][0][lrow] : &Bs[0][0][lrow];
        pl[0*132]=r0.x; pl[1*132]=r0.y; pl[2*132]=r0.z; pl[3*132]=r0.w;
        pl[4*132]=r1.x; pl[5*132]=r1.y; pl[6*132]=r1.z; pl[7*132]=r1.w;
        pl[8*132]=r2.x; pl[9*132]=r2.y; pl[10*132]=r2.z; pl[11*132]=r2.w;
        pl[12*132]=r3.x; pl[13*132]=r3.y; pl[14*132]=r3.z; pl[15*132]=r3.w;
    }
    __syncthreads();

    int buf = 0;
    for (int k0 = 16; k0 <= K; k0 += 16) {
        // prefetch next k-tile into registers
        if (k0 < K) {
            r0 = *(const float4*)(Lp + k0 + 0);
            r1 = *(const float4*)(Lp + k0 + 4);
            r2 = *(const float4*)(Lp + k0 + 8);
            r3 = *(const float4*)(Lp + k0 + 12);
        }
        // FMA over current buffer
        #pragma unroll
        for (int k = 0; k < 16; ++k) {
            float a[8], bb[8];
            *(float4*)&a[0]  = *(const float4*)&As[buf][k][ty*8];
            *(float4*)&a[4]  = *(const float4*)&As[buf][k][ty*8+4];
            *(float4*)&bb[0] = *(const float4*)&Bs[buf][k][tx*8];
            *(float4*)&bb[4] = *(const float4*)&Bs[buf][k][tx*8+4];
            #pragma unroll
            for (int i = 0; i < 8; ++i)
                #pragma unroll
                for (int j = 0; j < 8; ++j)
                    acc[i][j] += a[i] * bb[j];
        }
        // store prefetched tile to other buffer
        if (k0 < K) {
            float* pl = isA ? &As[buf^1][0][lrow] : &Bs[buf^1][0][lrow];
            pl[0*132]=r0.x; pl[1*132]=r0.y; pl[2*132]=r0.z; pl[3*132]=r0.w;
            pl[4*132]=r1.x; pl[5*132]=r1.y; pl[6*132]=r1.z; pl[7*132]=r1.w;
            pl[8*132]=r2.x; pl[9*132]=r2.y; pl[10*132]=r2.z; pl[11*132]=r2.w;
            pl[12*132]=r3.x; pl[13*132]=r3.y; pl[14*132]=r3.z; pl[15*132]=r3.w;
        }
        __syncthreads();
        buf ^= 1;
    }

    #pragma unroll
    for (int i = 0; i < 8; ++i) {
        int mm = m0 + ty*8 + i;
        #pragma unroll
        for (int j = 0; j < 8; ++j) {
            int nn = n0 + tx*8 + j;
            float v = acc[i][j];
            if (bias) v += bias[nn];
            C[(size_t)mm * ldc + nn] = v;
        }
    }
}

// ---------------- scores: S[b,h,n,m] = 0.125 * q[b,h,n,:] . k[b,h,m,:] ----------------
__global__ __launch_bounds__(256) void scores_kernel(
    const float* __restrict__ Y, float* __restrict__ S)
{
    __shared__ float Qs[64][68];
    __shared__ float Ks[64][68];
    const int z = blockIdx.z;             // b*H + h
    const int b = z / Hh, h = z % Hh;
    const int m0 = blockIdx.y * 64;       // query tile
    const int n0 = blockIdx.x * 64;       // key tile
    const int tid = threadIdx.x;
    const int row = tid >> 2, cbase = (tid & 3) * 16;

    const int qr = m0 + row;
    const int kr = n0 + row;
    const bool qok = qr < Nn, kok = kr < Nn;
    const float* qp = Y + (size_t)(b*Nn + qr) * QKVC + h*DhD;
    const float* kp = Y + (size_t)(b*Nn + kr) * QKVC + Cc + h*DhD;
    #pragma unroll
    for (int j = 0; j < 4; ++j) {
        int col = cbase + j*4;
        float4 qa = qok ? *(const float4*)(qp + col) : make_float4(0,0,0,0);
        float4 ka = kok ? *(const float4*)(kp + col) : make_float4(0,0,0,0);
        Qs[col+0][row]=qa.x; Qs[col+1][row]=qa.y; Qs[col+2][row]=qa.z; Qs[col+3][row]=qa.w;
        Ks[col+0][row]=ka.x; Ks[col+1][row]=ka.y; Ks[col+2][row]=ka.z; Ks[col+3][row]=ka.w;
    }
    __syncthreads();

    const int ty = tid >> 4, tx = tid & 15;
    float acc[4][4] = {};
    #pragma unroll
    for (int k = 0; k < 64; ++k) {
        float4 av = *(const float4*)&Qs[k][ty*4];
        float4 bv = *(const float4*)&Ks[k][tx*4];
        float am[4] = {av.x, av.y, av.z, av.w};
        float bm[4] = {bv.x, bv.y, bv.z, bv.w};
        #pragma unroll
        for (int i = 0; i < 4; ++i)
            #pragma unroll
            for (int j = 0; j < 4; ++j)
                acc[i][j] += am[i] * bm[j];
    }
    #pragma unroll
    for (int i = 0; i < 4; ++i) {
        int nq = m0 + ty*4 + i;
        if (nq >= Nn) continue;
        #pragma unroll
        for (int j = 0; j < 4; ++j) {
            int mk = n0 + tx*4 + j;
            if (mk >= Nn) continue;
            S[((size_t)z * Nn + nq) * Nn + mk] = acc[i][j] * 0.125f;
        }
    }
}

// ---------------- zero score_delta region ----------------
__global__ void zero_kernel(float4* __restrict__ p, int n4)
{
    int i = blockIdx.x * blockDim.x + threadIdx.x;
    if (i < n4) p[i] = make_float4(0.f, 0.f, 0.f, 0.f);
}

// ---------------- per-row UCB top-k + pruned-softmax context + score_delta ----------------
// Top-100 via 4-pass byte histogram radix select; warp-shuffle suffix sums.
__global__ __launch_bounds__(256) void topk_ctx_kernel(
    const float* __restrict__ Y,
    const float* __restrict__ S,
    const float* __restrict__ ucb,
    const int* __restrict__ counter_p,
    float* __restrict__ ctx,
    float* __restrict__ sd)
{
    __shared__ float    s_val[Nn];
    __shared__ unsigned s_key[Nn];
    __shared__ int      hist[256];
    __shared__ int      wtot[8];
    __shared__ int      wsuf[9];
    __shared__ int      sel_idx[TOPKK];
    __shared__ float    sel_w[TOPKK];
    __shared__ unsigned s_state[2];   // [0]=prefix, [1]=want
    __shared__ float    s_inv;
    __shared__ float    part[4][DhD];

    const int bid = blockIdx.x;
    const int n = bid % Nn;
    const int z = bid / Nn;                // b*H + h
    const int b = z / Hh, h = z % Hh;
    const int tid = threadIdx.x;
    const int lane = tid & 31, wrp = tid >> 5;

    const float logc = logf((float)(*counter_p));

    hist[tid] = 0;
    __syncthreads();

    // load row: raw score + orderable key of (score + ucb bonus); hist top byte
    const float* srow = S + ((size_t)z * Nn + n) * Nn;
    const float* urow = ucb + ((size_t)h * Nn + n) * Nn;
    for (int i = tid; i < Nn; i += 256) {
        float s = srow[i];
        float u = s + sqrtf(logc / (urow[i] + 1e-6f));
        s_val[i] = s;
        unsigned ub = __float_as_uint(u);
        unsigned key = (ub & 0x80000000u) ? ~ub : (ub | 0x80000000u);
        s_key[i] = key;
        atomicAdd(&hist[key >> 24], 1);
    }
    __syncthreads();

    // 4-pass radix select: find exact key of the 100th-largest element
    unsigned prefix = 0; int want = TOPKK;
    #pragma unroll
    for (int pass = 3; pass >= 0; --pass) {
        const int shift = pass * 8;
        if (pass < 3) {
            hist[tid] = 0;
            __syncthreads();
            const int hishift = shift + 8;
            const unsigned hipfx = prefix >> hishift;
            for (int i = tid; i < Nn; i += 256) {
                unsigned key = s_key[i];
                if ((key >> hishift) == hipfx)
                    atomicAdd(&hist[(key >> shift) & 0xFFu], 1);
            }
            __syncthreads();
        }
        // suffix sums via warp shuffles: sge(bin) = #candidates with byte >= bin
        int v = hist[tid];
        int suf = v;
        #pragma unroll
        for (int off = 1; off < 32; off <<= 1) {
            int t = __shfl_down_sync(0xffffffffu, suf, off);
            if (lane + off < 32) suf += t;
        }
        if (lane == 0) wtot[wrp] = suf;
        __syncthreads();
        if (tid < 8) {
            int sacc = 0;
            for (int w = tid; w < 8; ++w) sacc += wtot[w];
            wsuf[tid] = sacc;
        }
        if (tid == 0) wsuf[8] = 0;
        __syncthreads();
        int sge = suf + wsuf[wrp + 1];
        // crossing bucket: sge >= want && sge - v < want  (unique; requires v>0)
        if (sge >= want && sge - v < want) {
            s_state[0] = prefix | ((unsigned)tid << shift);
            s_state[1] = (unsigned)(want - (sge - v));
        }
        __syncthreads();
        prefix = s_state[0];
        want = (int)s_state[1];
        __syncthreads();
    }
    const unsigned tkey = prefix;   // exact key of k-th largest; `want` ties still needed

    // warp 0: deterministic index-ordered compaction (+ exact tie handling, lowest index first)
    if (tid < 32) {
        int cnt = 0, eq_seen = 0;
        const int need_eq = want;
        for (int base = 0; base < Nn; base += 32) {
            int i = base + lane;
            unsigned key = (i < Nn) ? s_key[i] : 0u;
            bool gt = (i < Nn) && (key > tkey);
            bool eq = (i < Nn) && (key == tkey);
            unsigned eqm = __ballot_sync(0xffffffffu, eq);
            int eq_rank = __popc(eqm & ((1u << lane) - 1u));
            bool sel = gt || (eq && (eq_seen + eq_rank) < need_eq);
            unsigned selm = __ballot_sync(0xffffffffu, sel);
            int pos = cnt + __popc(selm & ((1u << lane) - 1u));
            if (sel && pos < TOPKK) sel_idx[pos] = i;
            cnt += __popc(selm);
            eq_seen += __popc(eqm);
        }
        // deterministic sum of selected raw scores
        float ssum = 0.f;
        for (int j = lane; j < TOPKK; j += 32) ssum += s_val[sel_idx[j]];
        #pragma unroll
        for (int o = 16; o; o >>= 1) ssum += __shfl_xor_sync(0xffffffffu, ssum, o);
        if (lane == 0) s_inv = 1.0f / (ssum + 1e-8f);
    }
    __syncthreads();

    // normalized weights + score_delta
    if (tid < TOPKK) {
        sel_w[tid] = s_val[sel_idx[tid]] * s_inv;
        atomicAdd(&sd[((size_t)h * Nn + n) * Nn + sel_idx[tid]], 1.0f);
    }
    __syncthreads();

    // context gather: ctx[b,n,h*64+d] = sum_j w_j * v[b,j,h,d]
    const int d = tid & 63, g = tid >> 6;  // 4 groups of 25 selected each
    float acc = 0.f;
    const float* vbase = Y + (size_t)(b * Nn) * QKVC + 2*Cc + h*DhD + d;
    #pragma unroll 5
    for (int j = g*25; j < g*25 + 25; ++j)
        acc += sel_w[j] * vbase[(size_t)sel_idx[j] * QKVC];
    part[g][d] = acc;
    __syncthreads();
    if (tid < DhD) {
        float v = (part[0][tid] + part[1][tid]) + (part[2][tid] + part[3][tid]);
        ctx[((size_t)(b*Nn + n)) * Cc + h*DhD + tid] = v;
    }
}

extern "C" void kernel_launch(void* const* d_in, const int* in_sizes, int n_in,
                              void* d_out, int out_size)
{
    const float* x      = (const float*)d_in[0];
    const float* ucb    = (const float*)d_in[1];
    const float* qkv_w  = (const float*)d_in[2];
    const float* proj_w = (const float*)d_in[3];
    const float* proj_b = (const float*)d_in[4];
    const int*   counter = (const int*)d_in[5];
    float* out = (float*)d_out;
    float* sd  = out + (size_t)MROWS * Cc;   // score_delta region follows `out`

    float *Y, *S, *CTX;
    cudaGetSymbolAddress((void**)&Y,   g_Y);
    cudaGetSymbolAddress((void**)&S,   g_S);
    cudaGetSymbolAddress((void**)&CTX, g_CTX);

    // 1) qkv projection: Y[6272,2304] = x[6272,768] @ qkv_w[2304,768]^T
    gemm128_nt_kernel<<<dim3(QKVC/128, MROWS/128), 256>>>(x, Cc, qkv_w, Cc, Y, QKVC, Cc, nullptr);

    // 2) scores: 96 batched 784x784x64 GEMMs
    scores_kernel<<<dim3(13, 13, BHB), 256>>>(Y, S);

    // 3) zero score_delta
    {
        int n4 = (Hh * Nn * Nn) / 4;
        zero_kernel<<<(n4 + 255) / 256, 256>>>((float4*)sd, n4);
    }

    // 4) per-row top-100 + pruned normalize + context + score_delta
    topk_ctx_kernel<<<BHB * Nn, 256>>>(Y, S, ucb, counter, CTX, sd);

    // 5) output projection: out = CTX @ proj_w^T + proj_b
    gemm128_nt_kernel<<<dim3(Cc/128, MROWS/128), 256>>>(CTX, Cc, proj_w, Cc, out, Cc, Cc, proj_b);
}

// round 5
// speedup vs baseline: 1.5904x; 1.1450x over previous
#include <cuda_runtime.h>
#include <math.h>

#define Bx    8
#define Nn    784
#define Cc    768
#define Hh    12
#define DhD   64
#define TOPKK 100
#define MROWS (Bx*Nn)     // 6272
#define QKVC  (3*Cc)      // 2304
#define BHB   (Bx*Hh)     // 96
#define NCH   25          // ceil(784/32) chunks

// Scratch (allocation-free rule: __device__ globals)
__device__ float g_Y[(size_t)MROWS * QKVC];       // qkv projection output
__device__ float g_S[(size_t)BHB * Nn * Nn];      // raw scores (B,H,N,N)
__device__ float g_CTX[(size_t)MROWS * Cc];       // context in (B,N,C) layout

__device__ __forceinline__ float rsqrt_fast(float x) {
    float r; asm("rsqrt.approx.f32 %0, %1;" : "=f"(r) : "f"(x)); return r;
}

// ---------------- 128x128 NT GEMM: C[M,N] = A[M,K] * B[N,K]^T (+bias) ----------------
__global__ __launch_bounds__(256) void gemm128_nt_kernel(
    const float* __restrict__ A, int lda,
    const float* __restrict__ B, int ldb,
    float* __restrict__ C, int ldc,
    int K, const float* __restrict__ bias)
{
    __shared__ float As[2][16][132];
    __shared__ float Bs[2][16][132];
    const int m0 = blockIdx.y * 128, n0 = blockIdx.x * 128;
    const int tid = threadIdx.x;
    const int ty = tid >> 4, tx = tid & 15;

    const int lrow = tid & 127;
    const bool isA = tid < 128;
    const float* Lp = isA ? (A + (size_t)(m0 + lrow) * lda)
                          : (B + (size_t)(n0 + lrow) * ldb);

    float acc[8][8] = {};

    float4 r0 = *(const float4*)(Lp + 0);
    float4 r1 = *(const float4*)(Lp + 4);
    float4 r2 = *(const float4*)(Lp + 8);
    float4 r3 = *(const float4*)(Lp + 12);
    {
        float* pl = isA ? &As[0][0][lrow] : &Bs[0][0][lrow];
        pl[0*132]=r0.x; pl[1*132]=r0.y; pl[2*132]=r0.z; pl[3*132]=r0.w;
        pl[4*132]=r1.x; pl[5*132]=r1.y; pl[6*132]=r1.z; pl[7*132]=r1.w;
        pl[8*132]=r2.x; pl[9*132]=r2.y; pl[10*132]=r2.z; pl[11*132]=r2.w;
        pl[12*132]=r3.x; pl[13*132]=r3.y; pl[14*132]=r3.z; pl[15*132]=r3.w;
    }
    __syncthreads();

    int buf = 0;
    for (int k0 = 16; k0 <= K; k0 += 16) {
        if (k0 < K) {
            r0 = *(const float4*)(Lp + k0 + 0);
            r1 = *(const float4*)(Lp + k0 + 4);
            r2 = *(const float4*)(Lp + k0 + 8);
            r3 = *(const float4*)(Lp + k0 + 12);
        }
        #pragma unroll
        for (int k = 0; k < 16; ++k) {
            float a[8], bb[8];
            *(float4*)&a[0]  = *(const float4*)&As[buf][k][ty*8];
            *(float4*)&a[4]  = *(const float4*)&As[buf][k][ty*8+4];
            *(float4*)&bb[0] = *(const float4*)&Bs[buf][k][tx*8];
            *(float4*)&bb[4] = *(const float4*)&Bs[buf][k][tx*8+4];
            #pragma unroll
            for (int i = 0; i < 8; ++i)
                #pragma unroll
                for (int j = 0; j < 8; ++j)
                    acc[i][j] += a[i] * bb[j];
        }
        if (k0 < K) {
            float* pl = isA ? &As[buf^1][0][lrow] : &Bs[buf^1][0][lrow];
            pl[0*132]=r0.x; pl[1*132]=r0.y; pl[2*132]=r0.z; pl[3*132]=r0.w;
            pl[4*132]=r1.x; pl[5*132]=r1.y; pl[6*132]=r1.z; pl[7*132]=r1.w;
            pl[8*132]=r2.x; pl[9*132]=r2.y; pl[10*132]=r2.z; pl[11*132]=r2.w;
            pl[12*132]=r3.x; pl[13*132]=r3.y; pl[14*132]=r3.z; pl[15*132]=r3.w;
        }
        __syncthreads();
        buf ^= 1;
    }

    #pragma unroll
    for (int i = 0; i < 8; ++i) {
        int mm = m0 + ty*8 + i;
        #pragma unroll
        for (int j = 0; j < 8; ++j) {
            int nn = n0 + tx*8 + j;
            float v = acc[i][j];
            if (bias) v += bias[nn];
            C[(size_t)mm * ldc + nn] = v;
        }
    }
}

// ---------------- scores: S[b,h,n,m] = 0.125 * q[b,h,n,:] . k[b,h,m,:] ----------------
__global__ __launch_bounds__(256) void scores_kernel(
    const float* __restrict__ Y, float* __restrict__ S)
{
    __shared__ float Qs[64][68];
    __shared__ float Ks[64][68];
    const int z = blockIdx.z;             // b*H + h
    const int b = z / Hh, h = z % Hh;
    const int m0 = blockIdx.y * 64;
    const int n0 = blockIdx.x * 64;
    const int tid = threadIdx.x;
    const int row = tid >> 2, cbase = (tid & 3) * 16;

    const int qr = m0 + row;
    const int kr = n0 + row;
    const bool qok = qr < Nn, kok = kr < Nn;
    const float* qp = Y + (size_t)(b*Nn + qr) * QKVC + h*DhD;
    const float* kp = Y + (size_t)(b*Nn + kr) * QKVC + Cc + h*DhD;
    #pragma unroll
    for (int j = 0; j < 4; ++j) {
        int col = cbase + j*4;
        float4 qa = qok ? *(const float4*)(qp + col) : make_float4(0,0,0,0);
        float4 ka = kok ? *(const float4*)(kp + col) : make_float4(0,0,0,0);
        Qs[col+0][row]=qa.x; Qs[col+1][row]=qa.y; Qs[col+2][row]=qa.z; Qs[col+3][row]=qa.w;
        Ks[col+0][row]=ka.x; Ks[col+1][row]=ka.y; Ks[col+2][row]=ka.z; Ks[col+3][row]=ka.w;
    }
    __syncthreads();

    const int ty = tid >> 4, tx = tid & 15;
    float acc[4][4] = {};
    #pragma unroll
    for (int k = 0; k < 64; ++k) {
        float4 av = *(const float4*)&Qs[k][ty*4];
        float4 bv = *(const float4*)&Ks[k][tx*4];
        float am[4] = {av.x, av.y, av.z, av.w};
        float bm[4] = {bv.x, bv.y, bv.z, bv.w};
        #pragma unroll
        for (int i = 0; i < 4; ++i)
            #pragma unroll
            for (int j = 0; j < 4; ++j)
                acc[i][j] += am[i] * bm[j];
    }
    #pragma unroll
    for (int i = 0; i < 4; ++i) {
        int nq = m0 + ty*4 + i;
        if (nq >= Nn) continue;
        #pragma unroll
        for (int j = 0; j < 4; ++j) {
            int mk = n0 + tx*4 + j;
            if (mk >= Nn) continue;
            S[((size_t)z * Nn + nq) * Nn + mk] = acc[i][j] * 0.125f;
        }
    }
}

// ---------------- zero score_delta region ----------------
__global__ void zero_kernel(float4* __restrict__ p, int n4)
{
    int i = blockIdx.x * blockDim.x + threadIdx.x;
    if (i < n4) p[i] = make_float4(0.f, 0.f, 0.f, 0.f);
}

// ---------------- per-row UCB top-k + pruned-softmax context + score_delta ----------------
__global__ __launch_bounds__(256) void topk_ctx_kernel(
    const float* __restrict__ Y,
    const float* __restrict__ S,
    const float* __restrict__ ucb,
    const int* __restrict__ counter_p,
    float* __restrict__ ctx,
    float* __restrict__ sd)
{
    __shared__ float    s_val[Nn];
    __shared__ unsigned s_key[Nn];
    __shared__ int      hist[256];
    __shared__ int      wtot[8];
    __shared__ int      wsuf[9];
    __shared__ int      sel_idx[TOPKK];
    __shared__ float    sel_w[TOPKK];
    __shared__ unsigned s_state[2];   // [0]=prefix, [1]=want
    __shared__ float    s_inv;
    __shared__ unsigned gtm_s[NCH], eqm_s[NCH];
    __shared__ int      gt_off[NCH], eq_off[NCH];
    __shared__ int      s_totgt;
    __shared__ float    part[8][DhD];

    const int bid = blockIdx.x;
    const int n = bid % Nn;
    const int z = bid / Nn;                // b*H + h
    const int b = z / Hh, h = z % Hh;
    const int tid = threadIdx.x;
    const int lane = tid & 31, wrp = tid >> 5;

    const float sqb = sqrtf(logf((float)(*counter_p)));

    hist[tid] = 0;
    __syncthreads();

    // vectorized row load: raw scores + orderable keys of (score + ucb bonus)
    const float* srow = S + ((size_t)z * Nn + n) * Nn;
    const float* urow = ucb + ((size_t)h * Nn + n) * Nn;
    if (tid < Nn/4) {
        float4 s4 = ((const float4*)srow)[tid];
        float4 c4 = ((const float4*)urow)[tid];
        float u0 = s4.x + sqb * rsqrt_fast(c4.x + 1e-6f);
        float u1 = s4.y + sqb * rsqrt_fast(c4.y + 1e-6f);
        float u2 = s4.z + sqb * rsqrt_fast(c4.z + 1e-6f);
        float u3 = s4.w + sqb * rsqrt_fast(c4.w + 1e-6f);
        uint4 k4;
        unsigned ub;
        ub = __float_as_uint(u0); k4.x = (ub & 0x80000000u) ? ~ub : (ub | 0x80000000u);
        ub = __float_as_uint(u1); k4.y = (ub & 0x80000000u) ? ~ub : (ub | 0x80000000u);
        ub = __float_as_uint(u2); k4.z = (ub & 0x80000000u) ? ~ub : (ub | 0x80000000u);
        ub = __float_as_uint(u3); k4.w = (ub & 0x80000000u) ? ~ub : (ub | 0x80000000u);
        ((float4*)s_val)[tid] = s4;
        ((uint4*)s_key)[tid]  = k4;
        atomicAdd(&hist[k4.x >> 24], 1);
        atomicAdd(&hist[k4.y >> 24], 1);
        atomicAdd(&hist[k4.z >> 24], 1);
        atomicAdd(&hist[k4.w >> 24], 1);
    }
    __syncthreads();

    // 4-pass radix select: exact key of the 100th-largest element
    unsigned prefix = 0; int want = TOPKK;
    #pragma unroll
    for (int pass = 3; pass >= 0; --pass) {
        const int shift = pass * 8;
        if (pass < 3) {
            hist[tid] = 0;
            __syncthreads();
            const int hishift = shift + 8;
            const unsigned hipfx = prefix >> hishift;
            if (tid < Nn/4) {
                uint4 k4 = ((const uint4*)s_key)[tid];
                if ((k4.x >> hishift) == hipfx) atomicAdd(&hist[(k4.x >> shift) & 0xFFu], 1);
                if ((k4.y >> hishift) == hipfx) atomicAdd(&hist[(k4.y >> shift) & 0xFFu], 1);
                if ((k4.z >> hishift) == hipfx) atomicAdd(&hist[(k4.z >> shift) & 0xFFu], 1);
                if ((k4.w >> hishift) == hipfx) atomicAdd(&hist[(k4.w >> shift) & 0xFFu], 1);
            }
            __syncthreads();
        }
        // suffix sums via warp shuffles: sge(bin) = #candidates with byte >= bin
        int v = hist[tid];
        int suf = v;
        #pragma unroll
        for (int off = 1; off < 32; off <<= 1) {
            int t = __shfl_down_sync(0xffffffffu, suf, off);
            if (lane + off < 32) suf += t;
        }
        if (lane == 0) wtot[wrp] = suf;
        __syncthreads();
        if (tid < 8) {
            int sacc = 0;
            for (int w = tid; w < 8; ++w) sacc += wtot[w];
            wsuf[tid] = sacc;
        }
        if (tid == 0) wsuf[8] = 0;
        __syncthreads();
        int sge = suf + wsuf[wrp + 1];
        if (sge >= want && sge - v < want) {
            s_state[0] = prefix | ((unsigned)tid << shift);
            s_state[1] = (unsigned)(want - (sge - v));
        }
        __syncthreads();
        prefix = s_state[0];
        want = (int)s_state[1];
        __syncthreads();
    }
    const unsigned tkey = prefix;

    // parallel compaction, phase A: per-chunk ballots (all warps)
    for (int c = wrp; c < NCH; c += 8) {
        int i = c * 32 + lane;
        unsigned key = (i < Nn) ? s_key[i] : 0u;
        unsigned gtm = __ballot_sync(0xffffffffu, key > tkey);
        unsigned eqm = __ballot_sync(0xffffffffu, key == tkey);
        if (lane == 0) { gtm_s[c] = gtm; eqm_s[c] = eqm; }
    }
    __syncthreads();

    // phase B: exclusive prefix over 25 chunks (warp 0)
    if (tid < 32) {
        int gc = (lane < NCH) ? __popc(gtm_s[lane]) : 0;
        int ec = (lane < NCH) ? __popc(eqm_s[lane]) : 0;
        int gi = gc, ei = ec;
        #pragma unroll
        for (int off = 1; off < 32; off <<= 1) {
            int tg = __shfl_up_sync(0xffffffffu, gi, off);
            int te = __shfl_up_sync(0xffffffffu, ei, off);
            if (lane >= off) { gi += tg; ei += te; }
        }
        if (lane < NCH) { gt_off[lane] = gi - gc; eq_off[lane] = ei - ec; }
        if (lane == NCH - 1) s_totgt = gi;
    }
    __syncthreads();

    // phase C: positioned writes (selection set identical: all gt + first-`want` eq by index)
    const int totgt = s_totgt;
    for (int c = wrp; c < NCH; c += 8) {
        int i = c * 32 + lane;
        unsigned gtm = gtm_s[c], eqm = eqm_s[c];
        unsigned lm = (1u << lane) - 1u;
        if ((gtm >> lane) & 1u) {
            sel_idx[gt_off[c] + __popc(gtm & lm)] = i;
        } else if ((eqm >> lane) & 1u) {
            int er = eq_off[c] + __popc(eqm & lm);
            if (er < want) sel_idx[totgt + er] = i;
        }
    }
    __syncthreads();

    // deterministic sum of selected raw scores (warp 0, fixed order)
    if (tid < 32) {
        float ssum = 0.f;
        for (int j = lane; j < TOPKK; j += 32) ssum += s_val[sel_idx[j]];
        #pragma unroll
        for (int o = 16; o; o >>= 1) ssum += __shfl_xor_sync(0xffffffffu, ssum, o);
        if (lane == 0) s_inv = 1.0f / (ssum + 1e-8f);
    }
    __syncthreads();

    // normalized weights + score_delta
    if (tid < TOPKK) {
        sel_w[tid] = s_val[sel_idx[tid]] * s_inv;
        atomicAdd(&sd[((size_t)h * Nn + n) * Nn + sel_idx[tid]], 1.0f);
    }
    __syncthreads();

    // context gather: 8 groups x 32 lanes, float2 per lane
    {
        const int g = wrp;
        float2 acc = make_float2(0.f, 0.f);
        const float2* vb2 = (const float2*)(Y + (size_t)(b * Nn) * QKVC + 2*Cc + h*DhD) + lane;
        for (int j = g; j < TOPKK; j += 8) {
            float w = sel_w[j];
            float2 v = vb2[(size_t)sel_idx[j] * (QKVC/2)];
            acc.x += w * v.x;
            acc.y += w * v.y;
        }
        part[g][2*lane]   = acc.x;
        part[g][2*lane+1] = acc.y;
    }
    __syncthreads();
    if (tid < DhD) {
        float v = ((part[0][tid] + part[1][tid]) + (part[2][tid] + part[3][tid]))
                + ((part[4][tid] + part[5][tid]) + (part[6][tid] + part[7][tid]));
        ctx[((size_t)(b*Nn + n)) * Cc + h*DhD + tid] = v;
    }
}

extern "C" void kernel_launch(void* const* d_in, const int* in_sizes, int n_in,
                              void* d_out, int out_size)
{
    const float* x      = (const float*)d_in[0];
    const float* ucb    = (const float*)d_in[1];
    const float* qkv_w  = (const float*)d_in[2];
    const float* proj_w = (const float*)d_in[3];
    const float* proj_b = (const float*)d_in[4];
    const int*   counter = (const int*)d_in[5];
    float* out = (float*)d_out;
    float* sd  = out + (size_t)MROWS * Cc;   // score_delta region follows `out`

    float *Y, *S, *CTX;
    cudaGetSymbolAddress((void**)&Y,   g_Y);
    cudaGetSymbolAddress((void**)&S,   g_S);
    cudaGetSymbolAddress((void**)&CTX, g_CTX);

    // 1) qkv projection: Y[6272,2304] = x[6272,768] @ qkv_w[2304,768]^T
    gemm128_nt_kernel<<<dim3(QKVC/128, MROWS/128), 256>>>(x, Cc, qkv_w, Cc, Y, QKVC, Cc, nullptr);

    // 2) scores: 96 batched 784x784x64 GEMMs
    scores_kernel<<<dim3(13, 13, BHB), 256>>>(Y, S);

    // 3) zero score_delta
    {
        int n4 = (Hh * Nn * Nn) / 4;
        zero_kernel<<<(n4 + 255) / 256, 256>>>((float4*)sd, n4);
    }

    // 4) per-row top-100 + pruned normalize + context + score_delta
    topk_ctx_kernel<<<BHB * Nn, 256>>>(Y, S, ucb, counter, CTX, sd);

    // 5) output projection: out = CTX @ proj_w^T + proj_b
    gemm128_nt_kernel<<<dim3(Cc/128, MROWS/128), 256>>>(CTX, Cc, proj_w, Cc, out, Cc, Cc, proj_b);
}

// round 7
// speedup vs baseline: 1.6924x; 1.0642x over previous
#include <cuda_runtime.h>
#include <math.h>

#define Bx    8
#define Nn    784
#define Cc    768
#define Hh    12
#define DhD   64
#define TOPKK 100
#define MROWS (Bx*Nn)     // 6272
#define QKVC  (3*Cc)      // 2304
#define BHB   (Bx*Hh)     // 96
#define NCH   25          // ceil(784/32) chunks

// Scratch (allocation-free rule: __device__ globals)
__device__ float g_Y[(size_t)MROWS * QKVC];       // qkv projection output
__device__ float g_S[(size_t)BHB * Nn * Nn];      // raw scores (B,H,N,N)
__device__ float g_CTX[(size_t)MROWS * Cc];       // context in (B,N,C) layout

__device__ __forceinline__ float rsqrt_fast(float x) {
    float r; asm("rsqrt.approx.f32 %0, %1;" : "=f"(r) : "f"(x)); return r;
}
__device__ __forceinline__ unsigned f2tf(float x) {
    unsigned u; asm("cvt.rna.tf32.f32 %0, %1;" : "=r"(u) : "f"(x)); return u;
}
__device__ __forceinline__ void mma_tf32(float* d, const unsigned* a, const unsigned* b) {
    asm volatile("mma.sync.aligned.m16n8k8.row.col.f32.tf32.tf32.f32 "
        "{%0,%1,%2,%3}, {%4,%5,%6,%7}, {%8,%9}, {%0,%1,%2,%3};"
        : "+f"(d[0]), "+f"(d[1]), "+f"(d[2]), "+f"(d[3])
        : "r"(a[0]), "r"(a[1]), "r"(a[2]), "r"(a[3]), "r"(b[0]), "r"(b[1]));
}
__device__ __forceinline__ void split_store(float* H, float* L, int idx, float x) {
    float hf = __uint_as_float(f2tf(x));
    H[idx] = hf;
    L[idx] = __uint_as_float(f2tf(x - hf));
}

// ---------------- fp32 128x128 NT GEMM (bit-stable path for q,k) ----------------
__global__ __launch_bounds__(256) void gemm128_nt_kernel(
    const float* __restrict__ A, int lda,
    const float* __restrict__ B, int ldb,
    float* __restrict__ C, int ldc,
    int K, const float* __restrict__ bias)
{
    __shared__ float As[2][16][132];
    __shared__ float Bs[2][16][132];
    const int m0 = blockIdx.y * 128, n0 = blockIdx.x * 128;
    const int tid = threadIdx.x;
    const int ty = tid >> 4, tx = tid & 15;

    const int lrow = tid & 127;
    const bool isA = tid < 128;
    const float* Lp = isA ? (A + (size_t)(m0 + lrow) * lda)
                          : (B + (size_t)(n0 + lrow) * ldb);

    float acc[8][8] = {};

    float4 r0 = *(const float4*)(Lp + 0);
    float4 r1 = *(const float4*)(Lp + 4);
    float4 r2 = *(const float4*)(Lp + 8);
    float4 r3 = *(const float4*)(Lp + 12);
    {
        float* pl = isA ? &As[0][0][lrow] : &Bs[0][0][lrow];
        pl[0*132]=r0.x; pl[1*132]=r0.y; pl[2*132]=r0.z; pl[3*132]=r0.w;
        pl[4*132]=r1.x; pl[5*132]=r1.y; pl[6*132]=r1.z; pl[7*132]=r1.w;
        pl[8*132]=r2.x; pl[9*132]=r2.y; pl[10*132]=r2.z; pl[11*132]=r2.w;
        pl[12*132]=r3.x; pl[13*132]=r3.y; pl[14*132]=r3.z; pl[15*132]=r3.w;
    }
    __syncthreads();

    int buf = 0;
    for (int k0 = 16; k0 <= K; k0 += 16) {
        if (k0 < K) {
            r0 = *(const float4*)(Lp + k0 + 0);
            r1 = *(const float4*)(Lp + k0 + 4);
            r2 = *(const float4*)(Lp + k0 + 8);
            r3 = *(const float4*)(Lp + k0 + 12);
        }
        #pragma unroll
        for (int k = 0; k < 16; ++k) {
            float a[8], bb[8];
            *(float4*)&a[0]  = *(const float4*)&As[buf][k][ty*8];
            *(float4*)&a[4]  = *(const float4*)&As[buf][k][ty*8+4];
            *(float4*)&bb[0] = *(const float4*)&Bs[buf][k][tx*8];
            *(float4*)&bb[4] = *(const float4*)&Bs[buf][k][tx*8+4];
            #pragma unroll
            for (int i = 0; i < 8; ++i)
                #pragma unroll
                for (int j = 0; j < 8; ++j)
                    acc[i][j] += a[i] * bb[j];
        }
        if (k0 < K) {
            float* pl = isA ? &As[buf^1][0][lrow] : &Bs[buf^1][0][lrow];
            pl[0*132]=r0.x; pl[1*132]=r0.y; pl[2*132]=r0.z; pl[3*132]=r0.w;
            pl[4*132]=r1.x; pl[5*132]=r1.y; pl[6*132]=r1.z; pl[7*132]=r1.w;
            pl[8*132]=r2.x; pl[9*132]=r2.y; pl[10*132]=r2.z; pl[11*132]=r2.w;
            pl[12*132]=r3.x; pl[13*132]=r3.y; pl[14*132]=r3.z; pl[15*132]=r3.w;
        }
        __syncthreads();
        buf ^= 1;
    }

    #pragma unroll
    for (int i = 0; i < 8; ++i) {
        int mm = m0 + ty*8 + i;
        #pragma unroll
        for (int j = 0; j < 8; ++j) {
            int nn = n0 + tx*8 + j;
            float v = acc[i][j];
            if (bias) v += bias[nn];
            C[(size_t)mm * ldc + nn] = v;
        }
    }
}

// ---------------- tensor-core NT GEMM (3xTF32): flip-safe positions only ----------------
// Requires M%128==0, N%64==0, K%32==0. 256 threads, block tile 128x64, warp tile 32x32.
#define TG_LDS 36
#define TG_SMEM (((128+128+64+64)*TG_LDS)*4)
__global__ __launch_bounds__(256) void gemm_tf32_nt_kernel(
    const float* __restrict__ A, int lda,
    const float* __restrict__ B, int ldb,
    float* __restrict__ C, int ldc,
    int K, const float* __restrict__ bias)
{
    extern __shared__ float sm[];
    float* Ah = sm;                    // [128][36]
    float* Al = Ah + 128*TG_LDS;
    float* Bh = Al + 128*TG_LDS;       // [64][36]
    float* Bl = Bh + 64*TG_LDS;

    const int m0 = blockIdx.y * 128, n0 = blockIdx.x * 64;
    const int tid = threadIdx.x, lane = tid & 31, w = tid >> 5;
    const int mbase = (w >> 1) * 32, nbase = (w & 1) * 32;
    const int grp = lane >> 2, qd = lane & 3;

    float acc[2][4][4] = {};

    const int arow = tid >> 1, acol0 = (tid & 1) * 16;
    const int brow = tid >> 2, bcol0 = (tid & 3) * 8;
    const float* Ag = A + (size_t)(m0 + arow) * lda + acol0;
    const float* Bg = B + (size_t)(n0 + brow) * ldb + bcol0;

    for (int k0 = 0; k0 < K; k0 += 32) {
        #pragma unroll
        for (int j = 0; j < 4; ++j) {
            float4 v = *(const float4*)(Ag + k0 + j*4);
            int idx = arow * TG_LDS + acol0 + j*4;
            split_store(Ah, Al, idx+0, v.x);
            split_store(Ah, Al, idx+1, v.y);
            split_store(Ah, Al, idx+2, v.z);
            split_store(Ah, Al, idx+3, v.w);
        }
        #pragma unroll
        for (int j = 0; j < 2; ++j) {
            float4 v = *(const float4*)(Bg + k0 + j*4);
            int idx = brow * TG_LDS + bcol0 + j*4;
            split_store(Bh, Bl, idx+0, v.x);
            split_store(Bh, Bl, idx+1, v.y);
            split_store(Bh, Bl, idx+2, v.z);
            split_store(Bh, Bl, idx+3, v.w);
        }
        __syncthreads();
        #pragma unroll
        for (int ks = 0; ks < 4; ++ks) {
            const int kk = ks * 8;
            unsigned ah[2][4], al[2][4];
            #pragma unroll
            for (int mf = 0; mf < 2; ++mf) {
                int r = mbase + mf*16 + grp;
                int c = kk + qd;
                ah[mf][0] = __float_as_uint(Ah[r*TG_LDS + c]);
                ah[mf][1] = __float_as_uint(Ah[(r+8)*TG_LDS + c]);
                ah[mf][2] = __float_as_uint(Ah[r*TG_LDS + c + 4]);
                ah[mf][3] = __float_as_uint(Ah[(r+8)*TG_LDS + c + 4]);
                al[mf][0] = __float_as_uint(Al[r*TG_LDS + c]);
                al[mf][1] = __float_as_uint(Al[(r+8)*TG_LDS + c]);
                al[mf][2] = __float_as_uint(Al[r*TG_LDS + c + 4]);
                al[mf][3] = __float_as_uint(Al[(r+8)*TG_LDS + c + 4]);
            }
            #pragma unroll
            for (int nf = 0; nf < 4; ++nf) {
                int nr = nbase + nf*8 + grp;
                unsigned bhf[2] = { __float_as_uint(Bh[nr*TG_LDS + kk + qd]),
                                    __float_as_uint(Bh[nr*TG_LDS + kk + qd + 4]) };
                unsigned blf[2] = { __float_as_uint(Bl[nr*TG_LDS + kk + qd]),
                                    __float_as_uint(Bl[nr*TG_LDS + kk + qd + 4]) };
                #pragma unroll
                for (int mf = 0; mf < 2; ++mf) {
                    mma_tf32(acc[mf][nf], ah[mf], bhf);
                    mma_tf32(acc[mf][nf], ah[mf], blf);
                    mma_tf32(acc[mf][nf], al[mf], bhf);
                }
            }
        }
        __syncthreads();
    }

    #pragma unroll
    for (int mf = 0; mf < 2; ++mf) {
        int r = m0 + mbase + mf*16 + grp;
        #pragma unroll
        for (int nf = 0; nf < 4; ++nf) {
            int cidx = n0 + nbase + nf*8 + 2*qd;
            float b0 = bias ? bias[cidx]   : 0.f;
            float b1 = bias ? bias[cidx+1] : 0.f;
            *(float2*)&C[(size_t)r*ldc + cidx] =
                make_float2(acc[mf][nf][0] + b0, acc[mf][nf][1] + b1);
            *(float2*)&C[(size_t)(r+8)*ldc + cidx] =
                make_float2(acc[mf][nf][2] + b0, acc[mf][nf][3] + b1);
        }
    }
}

// ---------------- scores: S[b,h,n,m] = 0.125 * q[b,h,n,:] . k[b,h,m,:] ----------------
__global__ __launch_bounds__(256) void scores_kernel(
    const float* __restrict__ Y, float* __restrict__ S)
{
    __shared__ float Qs[64][68];
    __shared__ float Ks[64][68];
    const int z = blockIdx.z;             // b*H + h
    const int b = z / Hh, h = z % Hh;
    const int m0 = blockIdx.y * 64;
    const int n0 = blockIdx.x * 64;
    const int tid = threadIdx.x;
    const int row = tid >> 2, cbase = (tid & 3) * 16;

    const int qr = m0 + row;
    const int kr = n0 + row;
    const bool qok = qr < Nn, kok = kr < Nn;
    const float* qp = Y + (size_t)(b*Nn + qr) * QKVC + h*DhD;
    const float* kp = Y + (size_t)(b*Nn + kr) * QKVC + Cc + h*DhD;
    #pragma unroll
    for (int j = 0; j < 4; ++j) {
        int col = cbase + j*4;
        float4 qa = qok ? *(const float4*)(qp + col) : make_float4(0,0,0,0);
        float4 ka = kok ? *(const float4*)(kp + col) : make_float4(0,0,0,0);
        Qs[col+0][row]=qa.x; Qs[col+1][row]=qa.y; Qs[col+2][row]=qa.z; Qs[col+3][row]=qa.w;
        Ks[col+0][row]=ka.x; Ks[col+1][row]=ka.y; Ks[col+2][row]=ka.z; Ks[col+3][row]=ka.w;
    }
    __syncthreads();

    const int ty = tid >> 4, tx = tid & 15;
    float acc[4][4] = {};
    #pragma unroll
    for (int k = 0; k < 64; ++k) {
        float4 av = *(const float4*)&Qs[k][ty*4];
        float4 bv = *(const float4*)&Ks[k][tx*4];
        float am[4] = {av.x, av.y, av.z, av.w};
        float bm[4] = {bv.x, bv.y, bv.z, bv.w};
        #pragma unroll
        for (int i = 0; i < 4; ++i)
            #pragma unroll
            for (int j = 0; j < 4; ++j)
                acc[i][j] += am[i] * bm[j];
    }
    #pragma unroll
    for (int i = 0; i < 4; ++i) {
        int nq = m0 + ty*4 + i;
        if (nq >= Nn) continue;
        #pragma unroll
        for (int j = 0; j < 4; ++j) {
            int mk = n0 + tx*4 + j;
            if (mk >= Nn) continue;
            S[((size_t)z * Nn + nq) * Nn + mk] = acc[i][j] * 0.125f;
        }
    }
}

// ---------------- zero score_delta region ----------------
__global__ void zero_kernel(float4* __restrict__ p, int n4)
{
    int i = blockIdx.x * blockDim.x + threadIdx.x;
    if (i < n4) p[i] = make_float4(0.f, 0.f, 0.f, 0.f);
}

// ---------------- per-row UCB top-k + pruned-softmax context + score_delta ----------------
__global__ __launch_bounds__(256) void topk_ctx_kernel(
    const float* __restrict__ Y,
    const float* __restrict__ S,
    const float* __restrict__ ucb,
    const int* __restrict__ counter_p,
    float* __restrict__ ctx,
    float* __restrict__ sd)
{
    __shared__ float    s_val[Nn];
    __shared__ unsigned s_key[Nn];
    __shared__ int      hist[256];
    __shared__ int      wtot[8];
    __shared__ int      wsuf[9];
    __shared__ int      sel_idx[TOPKK];
    __shared__ float    sel_w[TOPKK];
    __shared__ unsigned s_state[2];   // [0]=prefix, [1]=want
    __shared__ float    s_inv;
    __shared__ unsigned gtm_s[NCH], eqm_s[NCH];
    __shared__ int      gt_off[NCH], eq_off[NCH];
    __shared__ int      s_totgt;
    __shared__ float    part[8][DhD];

    const int bid = blockIdx.x;
    const int n = bid % Nn;
    const int z = bid / Nn;                // b*H + h
    const int b = z / Hh, h = z % Hh;
    const int tid = threadIdx.x;
    const int lane = tid & 31, wrp = tid >> 5;

    const float sqb = sqrtf(logf((float)(*counter_p)));

    hist[tid] = 0;
    __syncthreads();

    // vectorized row load: raw scores + orderable keys of (score + ucb bonus)
    const float* srow = S + ((size_t)z * Nn + n) * Nn;
    const float* urow = ucb + ((size_t)h * Nn + n) * Nn;
    if (tid < Nn/4) {
        float4 s4 = ((const float4*)srow)[tid];
        float4 c4 = ((const float4*)urow)[tid];
        float u0 = s4.x + sqb * rsqrt_fast(c4.x + 1e-6f);
        float u1 = s4.y + sqb * rsqrt_fast(c4.y + 1e-6f);
        float u2 = s4.z + sqb * rsqrt_fast(c4.z + 1e-6f);
        float u3 = s4.w + sqb * rsqrt_fast(c4.w + 1e-6f);
        uint4 k4;
        unsigned ub;
        ub = __float_as_uint(u0); k4.x = (ub & 0x80000000u) ? ~ub : (ub | 0x80000000u);
        ub = __float_as_uint(u1); k4.y = (ub & 0x80000000u) ? ~ub : (ub | 0x80000000u);
        ub = __float_as_uint(u2); k4.z = (ub & 0x80000000u) ? ~ub : (ub | 0x80000000u);
        ub = __float_as_uint(u3); k4.w = (ub & 0x80000000u) ? ~ub : (ub | 0x80000000u);
        ((float4*)s_val)[tid] = s4;
        ((uint4*)s_key)[tid]  = k4;
        atomicAdd(&hist[k4.x >> 24], 1);
        atomicAdd(&hist[k4.y >> 24], 1);
        atomicAdd(&hist[k4.z >> 24], 1);
        atomicAdd(&hist[k4.w >> 24], 1);
    }
    __syncthreads();

    // 4-pass radix select: exact key of the 100th-largest element
    unsigned prefix = 0; int want = TOPKK;
    #pragma unroll
    for (int pass = 3; pass >= 0; --pass) {
        const int shift = pass * 8;
        if (pass < 3) {
            hist[tid] = 0;
            __syncthreads();
            const int hishift = shift + 8;
            const unsigned hipfx = prefix >> hishift;
            if (tid < Nn/4) {
                uint4 k4 = ((const uint4*)s_key)[tid];
                if ((k4.x >> hishift) == hipfx) atomicAdd(&hist[(k4.x >> shift) & 0xFFu], 1);
                if ((k4.y >> hishift) == hipfx) atomicAdd(&hist[(k4.y >> shift) & 0xFFu], 1);
                if ((k4.z >> hishift) == hipfx) atomicAdd(&hist[(k4.z >> shift) & 0xFFu], 1);
                if ((k4.w >> hishift) == hipfx) atomicAdd(&hist[(k4.w >> shift) & 0xFFu], 1);
            }
            __syncthreads();
        }
        int v = hist[tid];
        int suf = v;
        #pragma unroll
        for (int off = 1; off < 32; off <<= 1) {
            int t = __shfl_down_sync(0xffffffffu, suf, off);
            if (lane + off < 32) suf += t;
        }
        if (lane == 0) wtot[wrp] = suf;
        __syncthreads();
        if (tid < 8) {
            int sacc = 0;
            for (int w = tid; w < 8; ++w) sacc += wtot[w];
            wsuf[tid] = sacc;
        }
        if (tid == 0) wsuf[8] = 0;
        __syncthreads();
        int sge = suf + wsuf[wrp + 1];
        if (sge >= want && sge - v < want) {
            s_state[0] = prefix | ((unsigned)tid << shift);
            s_state[1] = (unsigned)(want - (sge - v));
        }
        __syncthreads();
        prefix = s_state[0];
        want = (int)s_state[1];
        __syncthreads();
    }
    const unsigned tkey = prefix;

    // parallel compaction, phase A: per-chunk ballots
    for (int c = wrp; c < NCH; c += 8) {
        int i = c * 32 + lane;
        unsigned key = (i < Nn) ? s_key[i] : 0u;
        unsigned gtm = __ballot_sync(0xffffffffu, key > tkey);
        unsigned eqm = __ballot_sync(0xffffffffu, key == tkey);
        if (lane == 0) { gtm_s[c] = gtm; eqm_s[c] = eqm; }
    }
    __syncthreads();

    // phase B: exclusive prefix over 25 chunks (warp 0)
    if (tid < 32) {
        int gc = (lane < NCH) ? __popc(gtm_s[lane]) : 0;
        int ec = (lane < NCH) ? __popc(eqm_s[lane]) : 0;
        int gi = gc, ei = ec;
        #pragma unroll
        for (int off = 1; off < 32; off <<= 1) {
            int tg = __shfl_up_sync(0xffffffffu, gi, off);
            int te = __shfl_up_sync(0xffffffffu, ei, off);
            if (lane >= off) { gi += tg; ei += te; }
        }
        if (lane < NCH) { gt_off[lane] = gi - gc; eq_off[lane] = ei - ec; }
        if (lane == NCH - 1) s_totgt = gi;
    }
    __syncthreads();

    // phase C: positioned writes
    const int totgt = s_totgt;
    for (int c = wrp; c < NCH; c += 8) {
        int i = c * 32 + lane;
        unsigned gtm = gtm_s[c], eqm = eqm_s[c];
        unsigned lm = (1u << lane) - 1u;
        if ((gtm >> lane) & 1u) {
            sel_idx[gt_off[c] + __popc(gtm & lm)] = i;
        } else if ((eqm >> lane) & 1u) {
            int er = eq_off[c] + __popc(eqm & lm);
            if (er < want) sel_idx[totgt + er] = i;
        }
    }
    __syncthreads();

    // deterministic sum of selected raw scores (warp 0, fixed order)
    if (tid < 32) {
        float ssum = 0.f;
        for (int j = lane; j < TOPKK; j += 32) ssum += s_val[sel_idx[j]];
        #pragma unroll
        for (int o = 16; o; o >>= 1) ssum += __shfl_xor_sync(0xffffffffu, ssum, o);
        if (lane == 0) s_inv = 1.0f / (ssum + 1e-8f);
    }
    __syncthreads();

    if (tid < TOPKK) {
        sel_w[tid] = s_val[sel_idx[tid]] * s_inv;
        atomicAdd(&sd[((size_t)h * Nn + n) * Nn + sel_idx[tid]], 1.0f);
    }
    __syncthreads();

    // context gather: 8 groups x 32 lanes, float2 per lane
    {
        const int g = wrp;
        float2 acc = make_float2(0.f, 0.f);
        const float2* vb2 = (const float2*)(Y + (size_t)(b * Nn) * QKVC + 2*Cc + h*DhD) + lane;
        for (int j = g; j < TOPKK; j += 8) {
            float w = sel_w[j];
            float2 v = vb2[(size_t)sel_idx[j] * (QKVC/2)];
            acc.x += w * v.x;
            acc.y += w * v.y;
        }
        part[g][2*lane]   = acc.x;
        part[g][2*lane+1] = acc.y;
    }
    __syncthreads();
    if (tid < DhD) {
        float v = ((part[0][tid] + part[1][tid]) + (part[2][tid] + part[3][tid]))
                + ((part[4][tid] + part[5][tid]) + (part[6][tid] + part[7][tid]));
        ctx[((size_t)(b*Nn + n)) * Cc + h*DhD + tid] = v;
    }
}

extern "C" void kernel_launch(void* const* d_in, const int* in_sizes, int n_in,
                              void* d_out, int out_size)
{
    const float* x      = (const float*)d_in[0];
    const float* ucb    = (const float*)d_in[1];
    const float* qkv_w  = (const float*)d_in[2];
    const float* proj_w = (const float*)d_in[3];
    const float* proj_b = (const float*)d_in[4];
    const int*   counter = (const int*)d_in[5];
    float* out = (float*)d_out;
    float* sd  = out + (size_t)MROWS * Cc;   // score_delta region follows `out`

    float *Y, *S, *CTX;
    cudaGetSymbolAddress((void**)&Y,   g_Y);
    cudaGetSymbolAddress((void**)&S,   g_S);
    cudaGetSymbolAddress((void**)&CTX, g_CTX);

    cudaFuncSetAttribute(gemm_tf32_nt_kernel,
                         cudaFuncAttributeMaxDynamicSharedMemorySize, TG_SMEM);

    // 1a) q,k projection (fp32, BIT-STABLE — feeds top-k selection):
    //     Y[:, 0:1536] = x @ qkv_w[0:1536,:]^T
    gemm128_nt_kernel<<<dim3((2*Cc)/128, MROWS/128), 256>>>(
        x, Cc, qkv_w, Cc, Y, QKVC, Cc, nullptr);

    // 1b) v projection (3xTF32 tensor — flip-safe, linear in output):
    //     Y[:, 1536:2304] = x @ qkv_w[1536:2304,:]^T
    gemm_tf32_nt_kernel<<<dim3(Cc/64, MROWS/128), 256, TG_SMEM>>>(
        x, Cc, qkv_w + (size_t)(2*Cc) * Cc, Cc, Y + 2*Cc, QKVC, Cc, nullptr);

    // 2) scores: 96 batched 784x784x64 GEMMs (fp32, bit-stable)
    scores_kernel<<<dim3(13, 13, BHB), 256>>>(Y, S);

    // 3) zero score_delta
    {
        int n4 = (Hh * Nn * Nn) / 4;
        zero_kernel<<<(n4 + 255) / 256, 256>>>((float4*)sd, n4);
    }

    // 4) per-row top-100 + pruned normalize + context + score_delta
    topk_ctx_kernel<<<BHB * Nn, 256>>>(Y, S, ucb, counter, CTX, sd);

    // 5) output projection: out = CTX @ proj_w^T + proj_b  (3xTF32 tensor, flip-safe)
    gemm_tf32_nt_kernel<<<dim3(Cc/64, MROWS/128), 256, TG_SMEM>>>(
        CTX, Cc, proj_w, Cc, out, Cc, Cc, proj_b);
}

// round 8
// speedup vs baseline: 1.9677x; 1.1627x over previous
#include <cuda_runtime.h>
#include <math.h>

#define Bx    8
#define Nn    784
#define Cc    768
#define Hh    12
#define DhD   64
#define TOPKK 100
#define MROWS (Bx*Nn)     // 6272
#define QKVC  (3*Cc)      // 2304
#define BHB   (Bx*Hh)     // 96
#define NCH   25          // ceil(784/32) chunks
#define RPW   8           // rows (warps) per block in topk

// Scratch (allocation-free rule: __device__ globals)
__device__ float g_Y[(size_t)MROWS * QKVC];       // qkv projection output
__device__ float g_S[(size_t)BHB * Nn * Nn];      // raw scores (B,H,N,N)
__device__ float g_CTX[(size_t)MROWS * Cc];       // context in (B,N,C) layout

__device__ __forceinline__ float rsqrt_fast(float x) {
    float r; asm("rsqrt.approx.f32 %0, %1;" : "=f"(r) : "f"(x)); return r;
}
__device__ __forceinline__ unsigned f2tf(float x) {
    unsigned u; asm("cvt.rna.tf32.f32 %0, %1;" : "=r"(u) : "f"(x)); return u;
}
__device__ __forceinline__ void mma_tf32(float* d, const unsigned* a, const unsigned* b) {
    asm volatile("mma.sync.aligned.m16n8k8.row.col.f32.tf32.tf32.f32 "
        "{%0,%1,%2,%3}, {%4,%5,%6,%7}, {%8,%9}, {%0,%1,%2,%3};"
        : "+f"(d[0]), "+f"(d[1]), "+f"(d[2]), "+f"(d[3])
        : "r"(a[0]), "r"(a[1]), "r"(a[2]), "r"(a[3]), "r"(b[0]), "r"(b[1]));
}
__device__ __forceinline__ void split_store(float* H, float* L, int idx, float x) {
    float hf = __uint_as_float(f2tf(x));
    H[idx] = hf;
    L[idx] = __uint_as_float(f2tf(x - hf));
}
__device__ __forceinline__ unsigned ord_key(float u) {
    unsigned ub = __float_as_uint(u);
    return (ub & 0x80000000u) ? ~ub : (ub | 0x80000000u);
}

// ---------------- fp32 128x128 NT GEMM (bit-stable path for q,k) ----------------
__global__ __launch_bounds__(256) void gemm128_nt_kernel(
    const float* __restrict__ A, int lda,
    const float* __restrict__ B, int ldb,
    float* __restrict__ C, int ldc,
    int K, const float* __restrict__ bias)
{
    __shared__ float As[2][16][132];
    __shared__ float Bs[2][16][132];
    const int m0 = blockIdx.y * 128, n0 = blockIdx.x * 128;
    const int tid = threadIdx.x;
    const int ty = tid >> 4, tx = tid & 15;

    const int lrow = tid & 127;
    const bool isA = tid < 128;
    const float* Lp = isA ? (A + (size_t)(m0 + lrow) * lda)
                          : (B + (size_t)(n0 + lrow) * ldb);

    float acc[8][8] = {};

    float4 r0 = *(const float4*)(Lp + 0);
    float4 r1 = *(const float4*)(Lp + 4);
    float4 r2 = *(const float4*)(Lp + 8);
    float4 r3 = *(const float4*)(Lp + 12);
    {
        float* pl = isA ? &As[0][0][lrow] : &Bs[0][0][lrow];
        pl[0*132]=r0.x; pl[1*132]=r0.y; pl[2*132]=r0.z; pl[3*132]=r0.w;
        pl[4*132]=r1.x; pl[5*132]=r1.y; pl[6*132]=r1.z; pl[7*132]=r1.w;
        pl[8*132]=r2.x; pl[9*132]=r2.y; pl[10*132]=r2.z; pl[11*132]=r2.w;
        pl[12*132]=r3.x; pl[13*132]=r3.y; pl[14*132]=r3.z; pl[15*132]=r3.w;
    }
    __syncthreads();

    int buf = 0;
    for (int k0 = 16; k0 <= K; k0 += 16) {
        if (k0 < K) {
            r0 = *(const float4*)(Lp + k0 + 0);
            r1 = *(const float4*)(Lp + k0 + 4);
            r2 = *(const float4*)(Lp + k0 + 8);
            r3 = *(const float4*)(Lp + k0 + 12);
        }
        #pragma unroll
        for (int k = 0; k < 16; ++k) {
            float a[8], bb[8];
            *(float4*)&a[0]  = *(const float4*)&As[buf][k][ty*8];
            *(float4*)&a[4]  = *(const float4*)&As[buf][k][ty*8+4];
            *(float4*)&bb[0] = *(const float4*)&Bs[buf][k][tx*8];
            *(float4*)&bb[4] = *(const float4*)&Bs[buf][k][tx*8+4];
            #pragma unroll
            for (int i = 0; i < 8; ++i)
                #pragma unroll
                for (int j = 0; j < 8; ++j)
                    acc[i][j] += a[i] * bb[j];
        }
        if (k0 < K) {
            float* pl = isA ? &As[buf^1][0][lrow] : &Bs[buf^1][0][lrow];
            pl[0*132]=r0.x; pl[1*132]=r0.y; pl[2*132]=r0.z; pl[3*132]=r0.w;
            pl[4*132]=r1.x; pl[5*132]=r1.y; pl[6*132]=r1.z; pl[7*132]=r1.w;
            pl[8*132]=r2.x; pl[9*132]=r2.y; pl[10*132]=r2.z; pl[11*132]=r2.w;
            pl[12*132]=r3.x; pl[13*132]=r3.y; pl[14*132]=r3.z; pl[15*132]=r3.w;
        }
        __syncthreads();
        buf ^= 1;
    }

    #pragma unroll
    for (int i = 0; i < 8; ++i) {
        int mm = m0 + ty*8 + i;
        #pragma unroll
        for (int j = 0; j < 8; ++j) {
            int nn = n0 + tx*8 + j;
            float v = acc[i][j];
            if (bias) v += bias[nn];
            C[(size_t)mm * ldc + nn] = v;
        }
    }
}

// ---------------- tensor-core NT GEMM (3xTF32): flip-safe positions only ----------------
#define TG_LDS 36
#define TG_SMEM (((128+128+64+64)*TG_LDS)*4)
__global__ __launch_bounds__(256) void gemm_tf32_nt_kernel(
    const float* __restrict__ A, int lda,
    const float* __restrict__ B, int ldb,
    float* __restrict__ C, int ldc,
    int K, const float* __restrict__ bias)
{
    extern __shared__ float sm[];
    float* Ah = sm;                    // [128][36]
    float* Al = Ah + 128*TG_LDS;
    float* Bh = Al + 128*TG_LDS;       // [64][36]
    float* Bl = Bh + 64*TG_LDS;

    const int m0 = blockIdx.y * 128, n0 = blockIdx.x * 64;
    const int tid = threadIdx.x, lane = tid & 31, w = tid >> 5;
    const int mbase = (w >> 1) * 32, nbase = (w & 1) * 32;
    const int grp = lane >> 2, qd = lane & 3;

    float acc[2][4][4] = {};

    const int arow = tid >> 1, acol0 = (tid & 1) * 16;
    const int brow = tid >> 2, bcol0 = (tid & 3) * 8;
    const float* Ag = A + (size_t)(m0 + arow) * lda + acol0;
    const float* Bg = B + (size_t)(n0 + brow) * ldb + bcol0;

    for (int k0 = 0; k0 < K; k0 += 32) {
        #pragma unroll
        for (int j = 0; j < 4; ++j) {
            float4 v = *(const float4*)(Ag + k0 + j*4);
            int idx = arow * TG_LDS + acol0 + j*4;
            split_store(Ah, Al, idx+0, v.x);
            split_store(Ah, Al, idx+1, v.y);
            split_store(Ah, Al, idx+2, v.z);
            split_store(Ah, Al, idx+3, v.w);
        }
        #pragma unroll
        for (int j = 0; j < 2; ++j) {
            float4 v = *(const float4*)(Bg + k0 + j*4);
            int idx = brow * TG_LDS + bcol0 + j*4;
            split_store(Bh, Bl, idx+0, v.x);
            split_store(Bh, Bl, idx+1, v.y);
            split_store(Bh, Bl, idx+2, v.z);
            split_store(Bh, Bl, idx+3, v.w);
        }
        __syncthreads();
        #pragma unroll
        for (int ks = 0; ks < 4; ++ks) {
            const int kk = ks * 8;
            unsigned ah[2][4], al[2][4];
            #pragma unroll
            for (int mf = 0; mf < 2; ++mf) {
                int r = mbase + mf*16 + grp;
                int c = kk + qd;
                ah[mf][0] = __float_as_uint(Ah[r*TG_LDS + c]);
                ah[mf][1] = __float_as_uint(Ah[(r+8)*TG_LDS + c]);
                ah[mf][2] = __float_as_uint(Ah[r*TG_LDS + c + 4]);
                ah[mf][3] = __float_as_uint(Ah[(r+8)*TG_LDS + c + 4]);
                al[mf][0] = __float_as_uint(Al[r*TG_LDS + c]);
                al[mf][1] = __float_as_uint(Al[(r+8)*TG_LDS + c]);
                al[mf][2] = __float_as_uint(Al[r*TG_LDS + c + 4]);
                al[mf][3] = __float_as_uint(Al[(r+8)*TG_LDS + c + 4]);
            }
            #pragma unroll
            for (int nf = 0; nf < 4; ++nf) {
                int nr = nbase + nf*8 + grp;
                unsigned bhf[2] = { __float_as_uint(Bh[nr*TG_LDS + kk + qd]),
                                    __float_as_uint(Bh[nr*TG_LDS + kk + qd + 4]) };
                unsigned blf[2] = { __float_as_uint(Bl[nr*TG_LDS + kk + qd]),
                                    __float_as_uint(Bl[nr*TG_LDS + kk + qd + 4]) };
                #pragma unroll
                for (int mf = 0; mf < 2; ++mf) {
                    mma_tf32(acc[mf][nf], ah[mf], bhf);
                    mma_tf32(acc[mf][nf], ah[mf], blf);
                    mma_tf32(acc[mf][nf], al[mf], bhf);
                }
            }
        }
        __syncthreads();
    }

    #pragma unroll
    for (int mf = 0; mf < 2; ++mf) {
        int r = m0 + mbase + mf*16 + grp;
        #pragma unroll
        for (int nf = 0; nf < 4; ++nf) {
            int cidx = n0 + nbase + nf*8 + 2*qd;
            float b0 = bias ? bias[cidx]   : 0.f;
            float b1 = bias ? bias[cidx+1] : 0.f;
            *(float2*)&C[(size_t)r*ldc + cidx] =
                make_float2(acc[mf][nf][0] + b0, acc[mf][nf][1] + b1);
            *(float2*)&C[(size_t)(r+8)*ldc + cidx] =
                make_float2(acc[mf][nf][2] + b0, acc[mf][nf][3] + b1);
        }
    }
}

// ---------------- scores: S[b,h,n,m] = 0.125 * q[b,h,n,:] . k[b,h,m,:] ----------------
__global__ __launch_bounds__(256) void scores_kernel(
    const float* __restrict__ Y, float* __restrict__ S)
{
    __shared__ float Qs[64][68];
    __shared__ float Ks[64][68];
    const int z = blockIdx.z;             // b*H + h
    const int b = z / Hh, h = z % Hh;
    const int m0 = blockIdx.y * 64;
    const int n0 = blockIdx.x * 64;
    const int tid = threadIdx.x;
    const int row = tid >> 2, cbase = (tid & 3) * 16;

    const int qr = m0 + row;
    const int kr = n0 + row;
    const bool qok = qr < Nn, kok = kr < Nn;
    const float* qp = Y + (size_t)(b*Nn + qr) * QKVC + h*DhD;
    const float* kp = Y + (size_t)(b*Nn + kr) * QKVC + Cc + h*DhD;
    #pragma unroll
    for (int j = 0; j < 4; ++j) {
        int col = cbase + j*4;
        float4 qa = qok ? *(const float4*)(qp + col) : make_float4(0,0,0,0);
        float4 ka = kok ? *(const float4*)(kp + col) : make_float4(0,0,0,0);
        Qs[col+0][row]=qa.x; Qs[col+1][row]=qa.y; Qs[col+2][row]=qa.z; Qs[col+3][row]=qa.w;
        Ks[col+0][row]=ka.x; Ks[col+1][row]=ka.y; Ks[col+2][row]=ka.z; Ks[col+3][row]=ka.w;
    }
    __syncthreads();

    const int ty = tid >> 4, tx = tid & 15;
    float acc[4][4] = {};
    #pragma unroll
    for (int k = 0; k < 64; ++k) {
        float4 av = *(const float4*)&Qs[k][ty*4];
        float4 bv = *(const float4*)&Ks[k][tx*4];
        float am[4] = {av.x, av.y, av.z, av.w};
        float bm[4] = {bv.x, bv.y, bv.z, bv.w};
        #pragma unroll
        for (int i = 0; i < 4; ++i)
            #pragma unroll
            for (int j = 0; j < 4; ++j)
                acc[i][j] += am[i] * bm[j];
    }
    #pragma unroll
    for (int i = 0; i < 4; ++i) {
        int nq = m0 + ty*4 + i;
        if (nq >= Nn) continue;
        #pragma unroll
        for (int j = 0; j < 4; ++j) {
            int mk = n0 + tx*4 + j;
            if (mk >= Nn) continue;
            S[((size_t)z * Nn + nq) * Nn + mk] = acc[i][j] * 0.125f;
        }
    }
}

// ---------------- zero score_delta region ----------------
__global__ void zero_kernel(float4* __restrict__ p, int n4)
{
    int i = blockIdx.x * blockDim.x + threadIdx.x;
    if (i < n4) p[i] = make_float4(0.f, 0.f, 0.f, 0.f);
}

// ---------------- warp-per-row UCB top-k + pruned-softmax context + score_delta ----------------
// One warp owns one (b,h,n) row end-to-end. Zero __syncthreads. Selection math
// (radix passes, tie handling, sum order) is bit-identical to the block version.
__global__ __launch_bounds__(256) void topk_ctx_warp_kernel(
    const float* __restrict__ Y,
    const float* __restrict__ S,
    const float* __restrict__ ucb,
    const int* __restrict__ counter_p,
    float* __restrict__ ctx,
    float* __restrict__ sd)
{
    __shared__ unsigned s_key[RPW][Nn];
    __shared__ int      s_hist[RPW][256];
    __shared__ int      s_sel[RPW][TOPKK];
    __shared__ float    s_w[RPW][TOPKK];

    const int lane = threadIdx.x & 31, wrp = threadIdx.x >> 5;
    const int row = blockIdx.x * RPW + wrp;
    const int n = row % Nn;
    const int z = row / Nn;                // b*H + h
    const int b = z / Hh, h = z % Hh;

    unsigned* keys = s_key[wrp];
    int*      hist = s_hist[wrp];
    int*      sel  = s_sel[wrp];
    float*    selw = s_w[wrp];

    const float sqb = sqrtf(logf((float)(*counter_p)));
    const unsigned FULL = 0xffffffffu;

    #pragma unroll
    for (int k = 0; k < 8; ++k) hist[lane*8 + k] = 0;
    __syncwarp();

    // load row, build keys + top-byte histogram (match-aggregated atomics)
    const float* srow = S + ((size_t)z * Nn + n) * Nn;
    const float* urow = ucb + ((size_t)h * Nn + n) * Nn;
    for (int j = lane; j < Nn/4; j += 32) {
        float4 s4 = ((const float4*)srow)[j];
        float4 c4 = ((const float4*)urow)[j];
        uint4 k4;
        k4.x = ord_key(s4.x + sqb * rsqrt_fast(c4.x + 1e-6f));
        k4.y = ord_key(s4.y + sqb * rsqrt_fast(c4.y + 1e-6f));
        k4.z = ord_key(s4.z + sqb * rsqrt_fast(c4.z + 1e-6f));
        k4.w = ord_key(s4.w + sqb * rsqrt_fast(c4.w + 1e-6f));
        ((uint4*)keys)[j] = k4;
        unsigned bins[4] = {k4.x >> 24, k4.y >> 24, k4.z >> 24, k4.w >> 24};
        unsigned act = __activemask();
        #pragma unroll
        for (int e = 0; e < 4; ++e) {
            unsigned mm = __match_any_sync(act, bins[e]);
            int leader = __ffs(mm) - 1;
            if (lane == leader) atomicAdd(&hist[bins[e]], __popc(mm));
        }
    }
    __syncwarp();

    // 4-pass radix select: exact key of the 100th-largest element
    unsigned prefix = 0; int want = TOPKK;
    #pragma unroll
    for (int pass = 3; pass >= 0; --pass) {
        const int shift = pass * 8;
        if (pass < 3) {
            #pragma unroll
            for (int k = 0; k < 8; ++k) hist[lane*8 + k] = 0;
            __syncwarp();
            const int hishift = shift + 8;
            const unsigned hipfx = prefix >> hishift;
            for (int j = lane; j < Nn/4; j += 32) {
                uint4 k4 = ((const uint4*)keys)[j];
                if ((k4.x >> hishift) == hipfx) atomicAdd(&hist[(k4.x >> shift) & 0xFFu], 1);
                if ((k4.y >> hishift) == hipfx) atomicAdd(&hist[(k4.y >> shift) & 0xFFu], 1);
                if ((k4.z >> hishift) == hipfx) atomicAdd(&hist[(k4.z >> shift) & 0xFFu], 1);
                if ((k4.w >> hishift) == hipfx) atomicAdd(&hist[(k4.w >> shift) & 0xFFu], 1);
            }
            __syncwarp();
        }
        // lane covers bins [8*lane, 8*lane+8); find crossing bucket warp-synchronously
        int hb[8]; int t = 0;
        #pragma unroll
        for (int k = 0; k < 8; ++k) { hb[k] = hist[lane*8 + k]; t += hb[k]; }
        int sfx = t;
        #pragma unroll
        for (int off = 1; off < 32; off <<= 1) {
            int tt = __shfl_down_sync(FULL, sfx, off);
            if (lane + off < 32) sfx += tt;
        }
        int acc_hi = sfx - t;   // sum over lanes > lane
        int cross = -1, cw = 0;
        #pragma unroll
        for (int k = 7; k >= 0; --k) {
            int sge = acc_hi + hb[k];
            if (sge >= want && acc_hi < want) { cross = lane*8 + k; cw = want - acc_hi; }
            acc_hi = sge;
        }
        unsigned m = __ballot_sync(FULL, cross >= 0);
        int src = __ffs(m) - 1;
        prefix |= ((unsigned)__shfl_sync(FULL, cross, src)) << shift;
        want = __shfl_sync(FULL, cw, src);
    }
    const unsigned tkey = prefix;

    // compaction: running-count, ascending index, exact tie handling (lowest index first)
    {
        int cnt = 0, eq_seen = 0;
        for (int c = 0; c < NCH; ++c) {
            int i = c*32 + lane;
            unsigned key = (i < Nn) ? keys[i] : 0u;
            bool gt = (i < Nn) && (key > tkey);
            bool eq = (i < Nn) && (key == tkey);
            unsigned eqm = __ballot_sync(FULL, eq);
            int eqr = __popc(eqm & ((1u << lane) - 1u));
            bool s = gt || (eq && (eq_seen + eqr) < want);
            unsigned smk = __ballot_sync(FULL, s);
            int pos = cnt + __popc(smk & ((1u << lane) - 1u));
            if (s && pos < TOPKK) sel[pos] = i;
            cnt += __popc(smk);
            eq_seen += __popc(eqm);
            if (cnt >= TOPKK) break;
        }
    }
    __syncwarp();

    // deterministic sum of selected raw scores (same lane-strided order as before)
    float ssum = 0.f;
    for (int j = lane; j < TOPKK; j += 32) {
        float v = srow[sel[j]];
        selw[j] = v;
        ssum += v;
    }
    #pragma unroll
    for (int o = 16; o; o >>= 1) ssum += __shfl_xor_sync(FULL, ssum, o);
    const float inv = 1.0f / (ssum + 1e-8f);
    __syncwarp();

    // normalized weights + score_delta
    for (int j = lane; j < TOPKK; j += 32) {
        selw[j] *= inv;
        atomicAdd(&sd[((size_t)h * Nn + n) * Nn + sel[j]], 1.0f);
    }
    __syncwarp();

    // context gather: whole row owned by this warp; lane covers 2 dims (float2)
    float2 acc = make_float2(0.f, 0.f);
    const float2* vb2 = (const float2*)(Y + (size_t)(b * Nn) * QKVC + 2*Cc + h*DhD) + lane;
    #pragma unroll 4
    for (int j = 0; j < TOPKK; ++j) {
        float w = selw[j];
        float2 v = vb2[(size_t)sel[j] * (QKVC/2)];
        acc.x += w * v.x;
        acc.y += w * v.y;
    }
    ((float2*)(ctx + ((size_t)(b*Nn + n)) * Cc + h*DhD))[lane] = acc;
}

extern "C" void kernel_launch(void* const* d_in, const int* in_sizes, int n_in,
                              void* d_out, int out_size)
{
    const float* x      = (const float*)d_in[0];
    const float* ucb    = (const float*)d_in[1];
    const float* qkv_w  = (const float*)d_in[2];
    const float* proj_w = (const float*)d_in[3];
    const float* proj_b = (const float*)d_in[4];
    const int*   counter = (const int*)d_in[5];
    float* out = (float*)d_out;
    float* sd  = out + (size_t)MROWS * Cc;   // score_delta region follows `out`

    float *Y, *S, *CTX;
    cudaGetSymbolAddress((void**)&Y,   g_Y);
    cudaGetSymbolAddress((void**)&S,   g_S);
    cudaGetSymbolAddress((void**)&CTX, g_CTX);

    cudaFuncSetAttribute(gemm_tf32_nt_kernel,
                         cudaFuncAttributeMaxDynamicSharedMemorySize, TG_SMEM);

    // 1a) q,k projection (fp32, BIT-STABLE — feeds top-k selection)
    gemm128_nt_kernel<<<dim3((2*Cc)/128, MROWS/128), 256>>>(
        x, Cc, qkv_w, Cc, Y, QKVC, Cc, nullptr);

    // 1b) v projection (3xTF32 tensor — flip-safe, linear in output)
    gemm_tf32_nt_kernel<<<dim3(Cc/64, MROWS/128), 256, TG_SMEM>>>(
        x, Cc, qkv_w + (size_t)(2*Cc) * Cc, Cc, Y + 2*Cc, QKVC, Cc, nullptr);

    // 2) scores: 96 batched 784x784x64 GEMMs (fp32, bit-stable, at FFMA floor)
    scores_kernel<<<dim3(13, 13, BHB), 256>>>(Y, S);

    // 3) zero score_delta
    {
        int n4 = (Hh * Nn * Nn) / 4;
        zero_kernel<<<(n4 + 255) / 256, 256>>>((float4*)sd, n4);
    }

    // 4) warp-per-row top-100 + pruned normalize + context + score_delta
    topk_ctx_warp_kernel<<<(BHB * Nn) / RPW, 32 * RPW>>>(Y, S, ucb, counter, CTX, sd);

    // 5) output projection: out = CTX @ proj_w^T + proj_b  (3xTF32 tensor, flip-safe)
    gemm_tf32_nt_kernel<<<dim3(Cc/64, MROWS/128), 256, TG_SMEM>>>(
        CTX, Cc, proj_w, Cc, out, Cc, Cc, proj_b);
}

// round 10
// speedup vs baseline: 1.9886x; 1.0106x over previous
#include <cuda_runtime.h>
#include <math.h>

#define Bx    8
#define Nn    784
#define Cc    768
#define Hh    12
#define DhD   64
#define TOPKK 100
#define MROWS (Bx*Nn)     // 6272
#define QKVC  (3*Cc)      // 2304
#define BHB   (Bx*Hh)     // 96
#define NCH   25          // ceil(784/32) chunks
#define RPW   8           // rows (warps) per block in topk

// Scratch (allocation-free rule: __device__ globals)
__device__ float g_Y[(size_t)MROWS * QKVC];       // qkv projection output
__device__ float g_S[(size_t)BHB * Nn * Nn];      // raw scores (B,H,N,N)
__device__ float g_CTX[(size_t)MROWS * Cc];       // context in (B,N,C) layout

__device__ __forceinline__ float rsqrt_fast(float x) {
    float r; asm("rsqrt.approx.f32 %0, %1;" : "=f"(r) : "f"(x)); return r;
}
__device__ __forceinline__ unsigned f2tf(float x) {
    unsigned u; asm("cvt.rna.tf32.f32 %0, %1;" : "=r"(u) : "f"(x)); return u;
}
__device__ __forceinline__ void mma_tf32(float* d, const unsigned* a, const unsigned* b) {
    asm volatile("mma.sync.aligned.m16n8k8.row.col.f32.tf32.tf32.f32 "
        "{%0,%1,%2,%3}, {%4,%5,%6,%7}, {%8,%9}, {%0,%1,%2,%3};"
        : "+f"(d[0]), "+f"(d[1]), "+f"(d[2]), "+f"(d[3])
        : "r"(a[0]), "r"(a[1]), "r"(a[2]), "r"(a[3]), "r"(b[0]), "r"(b[1]));
}
__device__ __forceinline__ void split_store(float* H, float* L, int idx, float x) {
    float hf = __uint_as_float(f2tf(x));
    H[idx] = hf;
    L[idx] = __uint_as_float(f2tf(x - hf));
}
__device__ __forceinline__ unsigned ord_key(float u) {
    unsigned ub = __float_as_uint(u);
    return (ub & 0x80000000u) ? ~ub : (ub | 0x80000000u);
}

// ---------------- fp32 128x128 NT GEMM (bit-stable path for q,k) ----------------
__global__ __launch_bounds__(256) void gemm128_nt_kernel(
    const float* __restrict__ A, int lda,
    const float* __restrict__ B, int ldb,
    float* __restrict__ C, int ldc,
    int K, const float* __restrict__ bias)
{
    __shared__ float As[2][16][132];
    __shared__ float Bs[2][16][132];
    const int m0 = blockIdx.y * 128, n0 = blockIdx.x * 128;
    const int tid = threadIdx.x;
    const int ty = tid >> 4, tx = tid & 15;

    const int lrow = tid & 127;
    const bool isA = tid < 128;
    const float* Lp = isA ? (A + (size_t)(m0 + lrow) * lda)
                          : (B + (size_t)(n0 + lrow) * ldb);

    float acc[8][8] = {};

    float4 r0 = *(const float4*)(Lp + 0);
    float4 r1 = *(const float4*)(Lp + 4);
    float4 r2 = *(const float4*)(Lp + 8);
    float4 r3 = *(const float4*)(Lp + 12);
    {
        float* pl = isA ? &As[0][0][lrow] : &Bs[0][0][lrow];
        pl[0*132]=r0.x; pl[1*132]=r0.y; pl[2*132]=r0.z; pl[3*132]=r0.w;
        pl[4*132]=r1.x; pl[5*132]=r1.y; pl[6*132]=r1.z; pl[7*132]=r1.w;
        pl[8*132]=r2.x; pl[9*132]=r2.y; pl[10*132]=r2.z; pl[11*132]=r2.w;
        pl[12*132]=r3.x; pl[13*132]=r3.y; pl[14*132]=r3.z; pl[15*132]=r3.w;
    }
    __syncthreads();

    int buf = 0;
    for (int k0 = 16; k0 <= K; k0 += 16) {
        if (k0 < K) {
            r0 = *(const float4*)(Lp + k0 + 0);
            r1 = *(const float4*)(Lp + k0 + 4);
            r2 = *(const float4*)(Lp + k0 + 8);
            r3 = *(const float4*)(Lp + k0 + 12);
        }
        #pragma unroll
        for (int k = 0; k < 16; ++k) {
            float a[8], bb[8];
            *(float4*)&a[0]  = *(const float4*)&As[buf][k][ty*8];
            *(float4*)&a[4]  = *(const float4*)&As[buf][k][ty*8+4];
            *(float4*)&bb[0] = *(const float4*)&Bs[buf][k][tx*8];
            *(float4*)&bb[4] = *(const float4*)&Bs[buf][k][tx*8+4];
            #pragma unroll
            for (int i = 0; i < 8; ++i)
                #pragma unroll
                for (int j = 0; j < 8; ++j)
                    acc[i][j] += a[i] * bb[j];
        }
        if (k0 < K) {
            float* pl = isA ? &As[buf^1][0][lrow] : &Bs[buf^1][0][lrow];
            pl[0*132]=r0.x; pl[1*132]=r0.y; pl[2*132]=r0.z; pl[3*132]=r0.w;
            pl[4*132]=r1.x; pl[5*132]=r1.y; pl[6*132]=r1.z; pl[7*132]=r1.w;
            pl[8*132]=r2.x; pl[9*132]=r2.y; pl[10*132]=r2.z; pl[11*132]=r2.w;
            pl[12*132]=r3.x; pl[13*132]=r3.y; pl[14*132]=r3.z; pl[15*132]=r3.w;
        }
        __syncthreads();
        buf ^= 1;
    }

    #pragma unroll
    for (int i = 0; i < 8; ++i) {
        int mm = m0 + ty*8 + i;
        #pragma unroll
        for (int j = 0; j < 8; ++j) {
            int nn = n0 + tx*8 + j;
            float v = acc[i][j];
            if (bias) v += bias[nn];
            C[(size_t)mm * ldc + nn] = v;
        }
    }
}

// ---------------- tensor-core NT GEMM (3xTF32): flip-safe positions only ----------------
#define TG_LDS 36
#define TG_SMEM (((128+128+64+64)*TG_LDS)*4)
__global__ __launch_bounds__(256) void gemm_tf32_nt_kernel(
    const float* __restrict__ A, int lda,
    const float* __restrict__ B, int ldb,
    float* __restrict__ C, int ldc,
    int K, const float* __restrict__ bias)
{
    extern __shared__ float sm[];
    float* Ah = sm;                    // [128][36]
    float* Al = Ah + 128*TG_LDS;
    float* Bh = Al + 128*TG_LDS;       // [64][36]
    float* Bl = Bh + 64*TG_LDS;

    const int m0 = blockIdx.y * 128, n0 = blockIdx.x * 64;
    const int tid = threadIdx.x, lane = tid & 31, w = tid >> 5;
    const int mbase = (w >> 1) * 32, nbase = (w & 1) * 32;
    const int grp = lane >> 2, qd = lane & 3;

    float acc[2][4][4] = {};

    const int arow = tid >> 1, acol0 = (tid & 1) * 16;
    const int brow = tid >> 2, bcol0 = (tid & 3) * 8;
    const float* Ag = A + (size_t)(m0 + arow) * lda + acol0;
    const float* Bg = B + (size_t)(n0 + brow) * ldb + bcol0;

    for (int k0 = 0; k0 < K; k0 += 32) {
        #pragma unroll
        for (int j = 0; j < 4; ++j) {
            float4 v = *(const float4*)(Ag + k0 + j*4);
            int idx = arow * TG_LDS + acol0 + j*4;
            split_store(Ah, Al, idx+0, v.x);
            split_store(Ah, Al, idx+1, v.y);
            split_store(Ah, Al, idx+2, v.z);
            split_store(Ah, Al, idx+3, v.w);
        }
        #pragma unroll
        for (int j = 0; j < 2; ++j) {
            float4 v = *(const float4*)(Bg + k0 + j*4);
            int idx = brow * TG_LDS + bcol0 + j*4;
            split_store(Bh, Bl, idx+0, v.x);
            split_store(Bh, Bl, idx+1, v.y);
            split_store(Bh, Bl, idx+2, v.z);
            split_store(Bh, Bl, idx+3, v.w);
        }
        __syncthreads();
        #pragma unroll
        for (int ks = 0; ks < 4; ++ks) {
            const int kk = ks * 8;
            unsigned ah[2][4], al[2][4];
            #pragma unroll
            for (int mf = 0; mf < 2; ++mf) {
                int r = mbase + mf*16 + grp;
                int c = kk + qd;
                ah[mf][0] = __float_as_uint(Ah[r*TG_LDS + c]);
                ah[mf][1] = __float_as_uint(Ah[(r+8)*TG_LDS + c]);
                ah[mf][2] = __float_as_uint(Ah[r*TG_LDS + c + 4]);
                ah[mf][3] = __float_as_uint(Ah[(r+8)*TG_LDS + c + 4]);
                al[mf][0] = __float_as_uint(Al[r*TG_LDS + c]);
                al[mf][1] = __float_as_uint(Al[(r+8)*TG_LDS + c]);
                al[mf][2] = __float_as_uint(Al[r*TG_LDS + c + 4]);
                al[mf][3] = __float_as_uint(Al[(r+8)*TG_LDS + c + 4]);
            }
            #pragma unroll
            for (int nf = 0; nf < 4; ++nf) {
                int nr = nbase + nf*8 + grp;
                unsigned bhf[2] = { __float_as_uint(Bh[nr*TG_LDS + kk + qd]),
                                    __float_as_uint(Bh[nr*TG_LDS + kk + qd + 4]) };
                unsigned blf[2] = { __float_as_uint(Bl[nr*TG_LDS + kk + qd]),
                                    __float_as_uint(Bl[nr*TG_LDS + kk + qd + 4]) };
                #pragma unroll
                for (int mf = 0; mf < 2; ++mf) {
                    mma_tf32(acc[mf][nf], ah[mf], bhf);
                    mma_tf32(acc[mf][nf], ah[mf], blf);
                    mma_tf32(acc[mf][nf], al[mf], bhf);
                }
            }
        }
        __syncthreads();
    }

    #pragma unroll
    for (int mf = 0; mf < 2; ++mf) {
        int r = m0 + mbase + mf*16 + grp;
        #pragma unroll
        for (int nf = 0; nf < 4; ++nf) {
            int cidx = n0 + nbase + nf*8 + 2*qd;
            float b0 = bias ? bias[cidx]   : 0.f;
            float b1 = bias ? bias[cidx+1] : 0.f;
            *(float2*)&C[(size_t)r*ldc + cidx] =
                make_float2(acc[mf][nf][0] + b0, acc[mf][nf][1] + b1);
            *(float2*)&C[(size_t)(r+8)*ldc + cidx] =
                make_float2(acc[mf][nf][2] + b0, acc[mf][nf][3] + b1);
        }
    }
}

// ---------------- scores: S[b,h,n,m] = 0.125 * q[b,h,n,:] . k[b,h,m,:] ----------------
__global__ __launch_bounds__(256) void scores_kernel(
    const float* __restrict__ Y, float* __restrict__ S)
{
    __shared__ float Qs[64][68];
    __shared__ float Ks[64][68];
    const int z = blockIdx.z;             // b*H + h
    const int b = z / Hh, h = z % Hh;
    const int m0 = blockIdx.y * 64;
    const int n0 = blockIdx.x * 64;
    const int tid = threadIdx.x;
    const int row = tid >> 2, cbase = (tid & 3) * 16;

    const int qr = m0 + row;
    const int kr = n0 + row;
    const bool qok = qr < Nn, kok = kr < Nn;
    const float* qp = Y + (size_t)(b*Nn + qr) * QKVC + h*DhD;
    const float* kp = Y + (size_t)(b*Nn + kr) * QKVC + Cc + h*DhD;
    #pragma unroll
    for (int j = 0; j < 4; ++j) {
        int col = cbase + j*4;
        float4 qa = qok ? *(const float4*)(qp + col) : make_float4(0,0,0,0);
        float4 ka = kok ? *(const float4*)(kp + col) : make_float4(0,0,0,0);
        Qs[col+0][row]=qa.x; Qs[col+1][row]=qa.y; Qs[col+2][row]=qa.z; Qs[col+3][row]=qa.w;
        Ks[col+0][row]=ka.x; Ks[col+1][row]=ka.y; Ks[col+2][row]=ka.z; Ks[col+3][row]=ka.w;
    }
    __syncthreads();

    const int ty = tid >> 4, tx = tid & 15;
    float acc[4][4] = {};
    #pragma unroll
    for (int k = 0; k < 64; ++k) {
        float4 av = *(const float4*)&Qs[k][ty*4];
        float4 bv = *(const float4*)&Ks[k][tx*4];
        float am[4] = {av.x, av.y, av.z, av.w};
        float bm[4] = {bv.x, bv.y, bv.z, bv.w};
        #pragma unroll
        for (int i = 0; i < 4; ++i)
            #pragma unroll
            for (int j = 0; j < 4; ++j)
                acc[i][j] += am[i] * bm[j];
    }
    #pragma unroll
    for (int i = 0; i < 4; ++i) {
        int nq = m0 + ty*4 + i;
        if (nq >= Nn) continue;
        #pragma unroll
        for (int j = 0; j < 4; ++j) {
            int mk = n0 + tx*4 + j;
            if (mk >= Nn) continue;
            S[((size_t)z * Nn + nq) * Nn + mk] = acc[i][j] * 0.125f;
        }
    }
}

// ---------------- zero score_delta region ----------------
__global__ void zero_kernel(float4* __restrict__ p, int n4)
{
    int i = blockIdx.x * blockDim.x + threadIdx.x;
    if (i < n4) p[i] = make_float4(0.f, 0.f, 0.f, 0.f);
}

// ---------------- warp-per-row UCB top-k + pruned-softmax context + score_delta ----------------
__global__ __launch_bounds__(256) void topk_ctx_warp_kernel(
    const float* __restrict__ Y,
    const float* __restrict__ S,
    const float* __restrict__ ucb,
    const int* __restrict__ counter_p,
    float* __restrict__ ctx,
    float* __restrict__ sd)
{
    __shared__ unsigned s_key[RPW][Nn];
    __shared__ int      s_hist[RPW][256];
    __shared__ int      s_sel[RPW][TOPKK];
    __shared__ float    s_w[RPW][TOPKK];

    const int lane = threadIdx.x & 31, wrp = threadIdx.x >> 5;
    const int row = blockIdx.x * RPW + wrp;
    const int n = row % Nn;
    const int z = row / Nn;                // b*H + h
    const int b = z / Hh, h = z % Hh;

    unsigned* keys = s_key[wrp];
    int*      hist = s_hist[wrp];
    int*      sel  = s_sel[wrp];
    float*    selw = s_w[wrp];

    const float sqb = sqrtf(logf((float)(*counter_p)));
    const unsigned FULL = 0xffffffffu;

    #pragma unroll
    for (int k = 0; k < 8; ++k) hist[lane*8 + k] = 0;
    __syncwarp();

    // load row, build keys + top-byte histogram (match-aggregated atomics)
    const float* srow = S + ((size_t)z * Nn + n) * Nn;
    const float* urow = ucb + ((size_t)h * Nn + n) * Nn;
    for (int j = lane; j < Nn/4; j += 32) {
        float4 s4 = ((const float4*)srow)[j];
        float4 c4 = ((const float4*)urow)[j];
        uint4 k4;
        k4.x = ord_key(s4.x + sqb * rsqrt_fast(c4.x + 1e-6f));
        k4.y = ord_key(s4.y + sqb * rsqrt_fast(c4.y + 1e-6f));
        k4.z = ord_key(s4.z + sqb * rsqrt_fast(c4.z + 1e-6f));
        k4.w = ord_key(s4.w + sqb * rsqrt_fast(c4.w + 1e-6f));
        ((uint4*)keys)[j] = k4;
        unsigned bins[4] = {k4.x >> 24, k4.y >> 24, k4.z >> 24, k4.w >> 24};
        unsigned act = __activemask();
        #pragma unroll
        for (int e = 0; e < 4; ++e) {
            unsigned mm = __match_any_sync(act, bins[e]);
            int leader = __ffs(mm) - 1;
            if (lane == leader) atomicAdd(&hist[bins[e]], __popc(mm));
        }
    }
    __syncwarp();

    // 4-pass radix select: exact key of the 100th-largest element
    unsigned prefix = 0; int want = TOPKK;
    #pragma unroll
    for (int pass = 3; pass >= 0; --pass) {
        const int shift = pass * 8;
        if (pass < 3) {
            #pragma unroll
            for (int k = 0; k < 8; ++k) hist[lane*8 + k] = 0;
            __syncwarp();
            const int hishift = shift + 8;
            const unsigned hipfx = prefix >> hishift;
            for (int j = lane; j < Nn/4; j += 32) {
                uint4 k4 = ((const uint4*)keys)[j];
                if ((k4.x >> hishift) == hipfx) atomicAdd(&hist[(k4.x >> shift) & 0xFFu], 1);
                if ((k4.y >> hishift) == hipfx) atomicAdd(&hist[(k4.y >> shift) & 0xFFu], 1);
                if ((k4.z >> hishift) == hipfx) atomicAdd(&hist[(k4.z >> shift) & 0xFFu], 1);
                if ((k4.w >> hishift) == hipfx) atomicAdd(&hist[(k4.w >> shift) & 0xFFu], 1);
            }
            __syncwarp();
        }
        int hb[8]; int t = 0;
        #pragma unroll
        for (int k = 0; k < 8; ++k) { hb[k] = hist[lane*8 + k]; t += hb[k]; }
        int sfx = t;
        #pragma unroll
        for (int off = 1; off < 32; off <<= 1) {
            int tt = __shfl_down_sync(FULL, sfx, off);
            if (lane + off < 32) sfx += tt;
        }
        int acc_hi = sfx - t;   // sum over lanes > lane
        int cross = -1, cw = 0;
        #pragma unroll
        for (int k = 7; k >= 0; --k) {
            int sge = acc_hi + hb[k];
            if (sge >= want && acc_hi < want) { cross = lane*8 + k; cw = want - acc_hi; }
            acc_hi = sge;
        }
        unsigned m = __ballot_sync(FULL, cross >= 0);
        int src = __ffs(m) - 1;
        prefix |= ((unsigned)__shfl_sync(FULL, cross, src)) << shift;
        want = __shfl_sync(FULL, cw, src);
    }
    const unsigned tkey = prefix;

    // compaction: running-count, ascending index, exact tie handling (lowest index first)
    {
        int cnt = 0, eq_seen = 0;
        for (int c = 0; c < NCH; ++c) {
            int i = c*32 + lane;
            unsigned key = (i < Nn) ? keys[i] : 0u;
            bool gt = (i < Nn) && (key > tkey);
            bool eq = (i < Nn) && (key == tkey);
            unsigned eqm = __ballot_sync(FULL, eq);
            int eqr = __popc(eqm & ((1u << lane) - 1u));
            bool s = gt || (eq && (eq_seen + eqr) < want);
            unsigned smk = __ballot_sync(FULL, s);
            int pos = cnt + __popc(smk & ((1u << lane) - 1u));
            if (s && pos < TOPKK) sel[pos] = i;
            cnt += __popc(smk);
            eq_seen += __popc(eqm);
            if (cnt >= TOPKK) break;
        }
    }
    __syncwarp();

    // deterministic sum of selected raw scores (same lane-strided order)
    float ssum = 0.f;
    for (int j = lane; j < TOPKK; j += 32) {
        float v = srow[sel[j]];
        selw[j] = v;
        ssum += v;
    }
    #pragma unroll
    for (int o = 16; o; o >>= 1) ssum += __shfl_xor_sync(FULL, ssum, o);
    const float inv = 1.0f / (ssum + 1e-8f);
    __syncwarp();

    // normalized weights + score_delta
    for (int j = lane; j < TOPKK; j += 32) {
        selw[j] *= inv;
        atomicAdd(&sd[((size_t)h * Nn + n) * Nn + sel[j]], 1.0f);
    }
    __syncwarp();

    // context gather: whole row owned by this warp; lane covers 2 dims (float2)
    float2 acc = make_float2(0.f, 0.f);
    const float2* vb2 = (const float2*)(Y + (size_t)(b * Nn) * QKVC + 2*Cc + h*DhD) + lane;
    #pragma unroll 4
    for (int j = 0; j < TOPKK; ++j) {
        float w = selw[j];
        float2 v = vb2[(size_t)sel[j] * (QKVC/2)];
        acc.x += w * v.x;
        acc.y += w * v.y;
    }
    ((float2*)(ctx + ((size_t)(b*Nn + n)) * Cc + h*DhD))[lane] = acc;
}

extern "C" void kernel_launch(void* const* d_in, const int* in_sizes, int n_in,
                              void* d_out, int out_size)
{
    const float* x      = (const float*)d_in[0];
    const float* ucb    = (const float*)d_in[1];
    const float* qkv_w  = (const float*)d_in[2];
    const float* proj_w = (const float*)d_in[3];
    const float* proj_b = (const float*)d_in[4];
    const int*   counter = (const int*)d_in[5];
    float* out = (float*)d_out;
    float* sd  = out + (size_t)MROWS * Cc;   // score_delta region follows `out`

    float *Y, *S, *CTX;
    cudaGetSymbolAddress((void**)&Y,   g_Y);
    cudaGetSymbolAddress((void**)&S,   g_S);
    cudaGetSymbolAddress((void**)&CTX, g_CTX);

    // lazy one-time handle creation (host-side handles only; no device memory)
    static cudaStream_t s_v = nullptr;
    static cudaEvent_t ev_fork = nullptr, ev_join = nullptr;
    if (s_v == nullptr) {
        cudaStreamCreateWithFlags(&s_v, cudaStreamNonBlocking);
        cudaEventCreateWithFlags(&ev_fork, cudaEventDisableTiming);
        cudaEventCreateWithFlags(&ev_join, cudaEventDisableTiming);
        cudaFuncSetAttribute(gemm_tf32_nt_kernel,
                             cudaFuncAttributeMaxDynamicSharedMemorySize, TG_SMEM);
    }

    // fork: side stream handles v-projection + sd zeroing (not on critical path)
    cudaEventRecord(ev_fork, 0);
    cudaStreamWaitEvent(s_v, ev_fork, 0);

    // side stream: v projection (3xTF32 tensor pipe — overlaps FFMA-bound main work)
    gemm_tf32_nt_kernel<<<dim3(Cc/64, MROWS/128), 256, TG_SMEM, s_v>>>(
        x, Cc, qkv_w + (size_t)(2*Cc) * Cc, Cc, Y + 2*Cc, QKVC, Cc, nullptr);
    {
        int n4 = (Hh * Nn * Nn) / 4;
        zero_kernel<<<(n4 + 255) / 256, 256, 0, s_v>>>((float4*)sd, n4);
    }
    cudaEventRecord(ev_join, s_v);

    // main stream: q,k projection (fp32, BIT-STABLE — feeds top-k selection)
    gemm128_nt_kernel<<<dim3((2*Cc)/128, MROWS/128), 256>>>(
        x, Cc, qkv_w, Cc, Y, QKVC, Cc, nullptr);

    // main stream: scores (fp32, bit-stable, at FFMA floor)
    scores_kernel<<<dim3(13, 13, BHB), 256>>>(Y, S);

    // join before topk (needs Y[v] and zeroed sd)
    cudaStreamWaitEvent(0, ev_join, 0);

    // warp-per-row top-100 + pruned normalize + context + score_delta
    topk_ctx_warp_kernel<<<(BHB * Nn) / RPW, 32 * RPW>>>(Y, S, ucb, counter, CTX, sd);

    // output projection: out = CTX @ proj_w^T + proj_b  (3xTF32 tensor, flip-safe)
    gemm_tf32_nt_kernel<<<dim3(Cc/64, MROWS/128), 256, TG_SMEM>>>(
        CTX, Cc, proj_w, Cc, out, Cc, Cc, proj_b);
}